// round 1
// baseline (speedup 1.0000x reference)
#include <cuda_runtime.h>
#include <cstdint>

#define NCTX 4096
#define DMODEL 2048

// Scratch (static device globals; no runtime allocation allowed)
__device__ float g_q[(size_t)NCTX * DMODEL];   // 32 MB
__device__ float g_s[(size_t)NCTX * NCTX];     // 64 MB (scores -> attn in place)
__device__ float g_z[(size_t)NCTX * DMODEL];   // 32 MB

constexpr int BM = 128, BN = 128, BK = 16, TM = 8, TN = 8;
constexpr int NTHR = 256;
constexpr int PAD = 4;

// Generic fp32 tiled GEMM: C[M,N] = A[M,K] * op(B)
//   BT=true : B is [N,K] row-major, C = A * B^T   (NT)
//   BT=false: B is [K,N] row-major, C = A * B     (NN)
//   CSKIP   : skip blocks entirely above the causal diagonal (scores GEMM)
//   CK      : limit K-loop to the causal extent (attn @ x GEMM)
template<bool BT, bool CSKIP, bool CK>
__global__ __launch_bounds__(NTHR)
void sgemm_k(const float* __restrict__ A, const float* __restrict__ B,
             float* __restrict__ C, int M, int N, int K,
             int lda, int ldb, int ldc)
{
    const int bx = blockIdx.x, by = blockIdx.y;
    if (CSKIP && bx * BN > by * BM + BM - 1) return;
    int Keff = K;
    if (CK) { int lim = (by + 1) * BM; Keff = lim < K ? lim : K; }

    __shared__ float As[BK][BM + PAD];
    __shared__ float Bs[BK][BN + PAD];

    const int tid = threadIdx.x;
    const int tx = tid & 15, ty = tid >> 4;

    const float* Ab = A + (size_t)by * BM * lda;
    const float* Bb = BT ? (B + (size_t)bx * BN * ldb) : (B + bx * BN);

    float acc[TM][TN];
    #pragma unroll
    for (int i = 0; i < TM; i++)
        #pragma unroll
        for (int j = 0; j < TN; j++) acc[i][j] = 0.f;

    const int lrow = tid >> 2;          // 0..63
    const int lcol = (tid & 3) * 4;     // 0,4,8,12

    for (int k0 = 0; k0 < Keff; k0 += BK) {
        // A tile: [BM x BK], loaded along K (coalesced), stored transposed
        #pragma unroll
        for (int r = 0; r < BM; r += 64) {
            float4 v = *(const float4*)(Ab + (size_t)(lrow + r) * lda + k0 + lcol);
            As[lcol + 0][lrow + r] = v.x;
            As[lcol + 1][lrow + r] = v.y;
            As[lcol + 2][lrow + r] = v.z;
            As[lcol + 3][lrow + r] = v.w;
        }
        if constexpr (BT) {
            // B tile from [N,K]: load along K, store transposed -> Bs[k][n]
            #pragma unroll
            for (int r = 0; r < BN; r += 64) {
                float4 v = *(const float4*)(Bb + (size_t)(lrow + r) * ldb + k0 + lcol);
                Bs[lcol + 0][lrow + r] = v.x;
                Bs[lcol + 1][lrow + r] = v.y;
                Bs[lcol + 2][lrow + r] = v.z;
                Bs[lcol + 3][lrow + r] = v.w;
            }
        } else {
            // B tile from [K,N]: already Bs[k][n] layout, coalesced along N
            const int brow = tid >> 5;          // 0..7
            const int bcol = (tid & 31) * 4;    // 0..124
            #pragma unroll
            for (int r = 0; r < BK; r += 8) {
                float4 v = *(const float4*)(Bb + (size_t)(k0 + brow + r) * ldb + bcol);
                *(float4*)(&Bs[brow + r][bcol]) = v;
            }
        }
        __syncthreads();

        #pragma unroll
        for (int k = 0; k < BK; k++) {
            float a[TM], b[TN];
            #pragma unroll
            for (int i = 0; i < TM; i += 4) {
                float4 t = *(const float4*)(&As[k][ty * TM + i]);
                a[i] = t.x; a[i + 1] = t.y; a[i + 2] = t.z; a[i + 3] = t.w;
            }
            #pragma unroll
            for (int j = 0; j < TN; j += 4) {
                float4 t = *(const float4*)(&Bs[k][tx * TN + j]);
                b[j] = t.x; b[j + 1] = t.y; b[j + 2] = t.z; b[j + 3] = t.w;
            }
            #pragma unroll
            for (int i = 0; i < TM; i++)
                #pragma unroll
                for (int j = 0; j < TN; j++)
                    acc[i][j] = fmaf(a[i], b[j], acc[i][j]);
        }
        __syncthreads();
    }

    #pragma unroll
    for (int i = 0; i < TM; i++) {
        float* Crow = C + (size_t)(by * BM + ty * TM + i) * ldc + bx * BN + tx * TN;
        *(float4*)(Crow)     = make_float4(acc[i][0], acc[i][1], acc[i][2], acc[i][3]);
        *(float4*)(Crow + 4) = make_float4(acc[i][4], acc[i][5], acc[i][6], acc[i][7]);
    }
}

__device__ __forceinline__ float warpMax(float v) {
    #pragma unroll
    for (int o = 16; o; o >>= 1) v = fmaxf(v, __shfl_xor_sync(0xffffffffu, v, o));
    return v;
}
__device__ __forceinline__ float warpSum(float v) {
    #pragma unroll
    for (int o = 16; o; o >>= 1) v += __shfl_xor_sync(0xffffffffu, v, o);
    return v;
}

// One block (256 threads) per row. Row i has i+1 valid columns.
// Writes normalized weights for j<=i, exact zeros for j in (i, ceil128(i+1)),
// so the causally K-limited GEMM3 reads only fully-defined data.
__global__ __launch_bounds__(NTHR)
void causal_softmax(float* __restrict__ S, int N)
{
    const int row = blockIdx.x;
    const int len = row + 1;
    float* Srow = S + (size_t)row * N;
    const int tid = threadIdx.x;

    float vals[16];
    int cnt = 0;
    float m = -3.4e38f;
    for (int j = tid; j < len; j += NTHR) {
        float v = Srow[j];
        vals[cnt++] = v;
        m = fmaxf(m, v);
    }

    __shared__ float red[8];
    m = warpMax(m);
    if ((tid & 31) == 0) red[tid >> 5] = m;
    __syncthreads();
    float bm = red[0];
    #pragma unroll
    for (int w = 1; w < 8; w++) bm = fmaxf(bm, red[w]);
    __syncthreads();

    float sum = 0.f;
    for (int c = 0; c < cnt; c++) {
        float e = __expf(vals[c] - bm);
        vals[c] = e;
        sum += e;
    }
    sum = warpSum(sum);
    if ((tid & 31) == 0) red[tid >> 5] = sum;
    __syncthreads();
    float bs = 0.f;
    #pragma unroll
    for (int w = 0; w < 8; w++) bs += red[w];
    const float inv = 1.0f / bs;

    cnt = 0;
    for (int j = tid; j < len; j += NTHR) Srow[j] = vals[cnt++] * inv;

    const int zend = (len + 127) & ~127;   // zero-fill to next 128 boundary
    for (int j = len + tid; j < zend; j += NTHR) Srow[j] = 0.f;
}

extern "C" void kernel_launch(void* const* d_in, const int* in_sizes, int n_in,
                              void* d_out, int out_size)
{
    const float* x   = (const float*)d_in[0];
    const float* Wqk = (const float*)d_in[1];
    const float* Wov = (const float*)d_in[2];
    float* out = (float*)d_out;

    float *q, *s, *z;
    cudaGetSymbolAddress((void**)&q, g_q);
    cudaGetSymbolAddress((void**)&s, g_s);
    cudaGetSymbolAddress((void**)&z, g_z);

    dim3 blk(NTHR);

    // 1) q = x @ Wqk^T   [4096 x 2048]
    sgemm_k<true, false, false><<<dim3(DMODEL / BN, NCTX / BM), blk>>>(
        x, Wqk, q, NCTX, DMODEL, DMODEL, DMODEL, DMODEL, DMODEL);

    // 2) s = q @ x^T     [4096 x 4096], upper-triangular blocks skipped
    sgemm_k<true, true, false><<<dim3(NCTX / BN, NCTX / BM), blk>>>(
        q, x, s, NCTX, NCTX, DMODEL, DMODEL, DMODEL, NCTX);

    // 3) causal softmax in place
    causal_softmax<<<NCTX, blk>>>(s, NCTX);

    // 4) z = attn @ x    [4096 x 2048], K-loop causally limited per row-block
    sgemm_k<false, false, true><<<dim3(DMODEL / BN, NCTX / BM), blk>>>(
        s, x, z, NCTX, DMODEL, NCTX, NCTX, DMODEL, DMODEL);

    // 5) out = z @ Wov^T [4096 x 2048]
    sgemm_k<true, false, false><<<dim3(DMODEL / BN, NCTX / BM), blk>>>(
        z, Wov, out, NCTX, DMODEL, DMODEL, DMODEL, DMODEL, DMODEL);
}

// round 3
// speedup vs baseline: 2.4255x; 2.4255x over previous
#include <cuda_runtime.h>
#include <cuda_fp16.h>
#include <cstdint>

#define NCTX 4096
#define DMODEL 2048

// ---------------- scratch (static device globals; no runtime alloc) ----------------
__device__ float g_s[(size_t)NCTX * NCTX];                        // 64 MB scores
__device__ __align__(256) __half g_xh[(size_t)NCTX * DMODEL];
__device__ __align__(256) __half g_xl[(size_t)NCTX * DMODEL];
__device__ __align__(256) __half g_xth[(size_t)DMODEL * NCTX];
__device__ __align__(256) __half g_xtl[(size_t)DMODEL * NCTX];
__device__ __align__(256) __half g_wqh[(size_t)DMODEL * DMODEL];
__device__ __align__(256) __half g_wql[(size_t)DMODEL * DMODEL];
__device__ __align__(256) __half g_wvh[(size_t)DMODEL * DMODEL];
__device__ __align__(256) __half g_wvl[(size_t)DMODEL * DMODEL];
__device__ __align__(256) __half g_qh[(size_t)NCTX * DMODEL];
__device__ __align__(256) __half g_ql[(size_t)NCTX * DMODEL];
__device__ __align__(256) __half g_ah[(size_t)NCTX * NCTX];
__device__ __align__(256) __half g_al[(size_t)NCTX * NCTX];
__device__ __align__(256) __half g_zh[(size_t)NCTX * DMODEL];
__device__ __align__(256) __half g_zl[(size_t)NCTX * DMODEL];

// ---------------- GEMM config ----------------
constexpr int BM = 128, BN = 128, BK = 32;          // halves
constexpr int TILE_B = BM * BK * 2;                 // 8192 B per matrix tile
constexpr int STAGE  = 4 * TILE_B;                  // Ah,Al,Bh,Bl = 32 KB
constexpr int SMEM_BYTES = 2 * STAGE;               // 64 KB

__device__ __forceinline__ uint32_t sm_addr(const void* p) {
    uint32_t a;
    asm("{ .reg .u64 t; cvta.to.shared.u64 t, %1; cvt.u32.u64 %0, t; }" : "=r"(a) : "l"(p));
    return a;
}
__device__ __forceinline__ void cpasync16(uint32_t s, const void* g) {
    asm volatile("cp.async.cg.shared.global [%0], [%1], 16;" :: "r"(s), "l"(g));
}
__device__ __forceinline__ void ldmx4(uint32_t& r0, uint32_t& r1, uint32_t& r2, uint32_t& r3,
                                      uint32_t a) {
    asm volatile("ldmatrix.sync.aligned.m8n8.x4.shared.b16 {%0,%1,%2,%3}, [%4];"
                 : "=r"(r0), "=r"(r1), "=r"(r2), "=r"(r3) : "r"(a));
}
__device__ __forceinline__ void mma16816(float* c, const uint32_t* a, const uint32_t* b) {
    asm volatile("mma.sync.aligned.m16n8k16.row.col.f32.f16.f16.f32 "
                 "{%0,%1,%2,%3}, {%4,%5,%6,%7}, {%8,%9}, {%0,%1,%2,%3};"
                 : "+f"(c[0]), "+f"(c[1]), "+f"(c[2]), "+f"(c[3])
                 : "r"(a[0]), "r"(a[1]), "r"(a[2]), "r"(a[3]), "r"(b[0]), "r"(b[1]));
}
// swizzled byte offset for (row, 16B-chunk j) in a 64B-per-row tile
__device__ __forceinline__ uint32_t swoff(int row, int j) {
    return row * 64 + ((j ^ ((row >> 1) & 3)) << 4);
}

// ---------------- split-precision fp16 NT GEMM via mma.sync ----------------
// C[M,N] = (Ah+Al)[M,K] * (Bh+Bl)[N,K]^T  (fp32 accumulate, 3 HMMA passes)
template<bool SPLIT_OUT, bool CSKIP, bool CK>
__global__ __launch_bounds__(256, 1)
void tgemm(const __half* __restrict__ Ah, const __half* __restrict__ Al,
           const __half* __restrict__ Bh, const __half* __restrict__ Bl,
           float* __restrict__ Cf, __half* __restrict__ Ch, __half* __restrict__ Cl,
           int K, int lda, int ldb, int ldc)
{
    const int bx = blockIdx.x, by = blockIdx.y;
    if (CSKIP && bx > by) return;                    // BM == BN == 128
    const int Keff = CK ? min(K, (by + 1) * BM) : K;
    const int nC = Keff / BK;

    extern __shared__ __align__(1024) char smem[];
    const uint32_t sb = sm_addr(smem);

    const int tid = threadIdx.x;
    const int lane = tid & 31, wid = tid >> 5;
    const int wm = wid & 1, wn = wid >> 1;           // warp grid 2(M) x 4(N)

    // --- load indexing: each thread moves 2 x 16B chunks per matrix tile ---
    const int lrow = tid >> 1;                       // 0..127
    const int ljb  = (tid & 1) * 2;                  // chunk base 0 or 2
    const size_t arow = (size_t)(by * BM + lrow) * lda;
    const size_t brow = (size_t)(bx * BN + lrow) * ldb;

    float acc[4][4][4];
    #pragma unroll
    for (int i = 0; i < 4; i++)
        #pragma unroll
        for (int j = 0; j < 4; j++)
            #pragma unroll
            for (int r = 0; r < 4; r++) acc[i][j][r] = 0.f;

    auto issue = [&](int c) {
        const uint32_t s0 = sb + (c & 1) * STAGE;
        const int kc = c * BK;
        #pragma unroll
        for (int jj = 0; jj < 2; jj++) {
            const int j = ljb + jj;
            const uint32_t so = swoff(lrow, j);
            const size_t ga = arow + kc + j * 8;
            const size_t gb = brow + kc + j * 8;
            cpasync16(s0 + so,              Ah + ga);
            cpasync16(s0 + TILE_B + so,     Al + ga);
            cpasync16(s0 + 2 * TILE_B + so, Bh + gb);
            cpasync16(s0 + 3 * TILE_B + so, Bl + gb);
        }
    };

    issue(0); asm volatile("cp.async.commit_group;");
    issue(1); asm volatile("cp.async.commit_group;");

    for (int c = 0; c < nC; c++) {
        asm volatile("cp.async.wait_group 1;");
        __syncthreads();
        const uint32_t s0 = sb + (c & 1) * STAGE;

        #pragma unroll
        for (int ks = 0; ks < 2; ks++) {
            uint32_t a_h[4][4], a_l[4][4], b_h[4][2], b_l[4][2];
            #pragma unroll
            for (int i = 0; i < 4; i++) {
                const int row = wm * 64 + i * 16 + (lane & 15);
                const int ch  = 2 * ks + (lane >> 4);
                const uint32_t off = swoff(row, ch);
                ldmx4(a_h[i][0], a_h[i][1], a_h[i][2], a_h[i][3], s0 + off);
                ldmx4(a_l[i][0], a_l[i][1], a_l[i][2], a_l[i][3], s0 + TILE_B + off);
            }
            #pragma unroll
            for (int p = 0; p < 2; p++) {
                const int row = wn * 32 + p * 16 + (lane & 7) + ((lane & 16) >> 1);
                const int ch  = 2 * ks + ((lane >> 3) & 1);
                const uint32_t off = swoff(row, ch);
                uint32_t r0, r1, r2, r3;
                ldmx4(r0, r1, r2, r3, s0 + 2 * TILE_B + off);
                b_h[2 * p][0] = r0; b_h[2 * p][1] = r1;
                b_h[2 * p + 1][0] = r2; b_h[2 * p + 1][1] = r3;
                ldmx4(r0, r1, r2, r3, s0 + 3 * TILE_B + off);
                b_l[2 * p][0] = r0; b_l[2 * p][1] = r1;
                b_l[2 * p + 1][0] = r2; b_l[2 * p + 1][1] = r3;
            }
            #pragma unroll
            for (int i = 0; i < 4; i++)
                #pragma unroll
                for (int j = 0; j < 4; j++) {
                    mma16816(acc[i][j], a_h[i], b_h[j]);
                    mma16816(acc[i][j], a_h[i], b_l[j]);
                    mma16816(acc[i][j], a_l[i], b_h[j]);
                }
        }
        __syncthreads();
        if (c + 2 < nC) issue(c + 2);
        asm volatile("cp.async.commit_group;");
    }

    // ---------------- epilogue ----------------
    const int r0 = by * BM + wm * 64 + (lane >> 2);
    const int c0 = bx * BN + wn * 32 + (lane & 3) * 2;
    #pragma unroll
    for (int i = 0; i < 4; i++)
        #pragma unroll
        for (int j = 0; j < 4; j++) {
            const int rr = r0 + i * 16;
            const int cc = c0 + j * 8;
            #pragma unroll
            for (int h = 0; h < 2; h++) {
                const float v0 = acc[i][j][2 * h], v1 = acc[i][j][2 * h + 1];
                const size_t o = (size_t)(rr + 8 * h) * ldc + cc;
                if (!SPLIT_OUT) {
                    *(float2*)(Cf + o) = make_float2(v0, v1);
                } else {
                    __half h0 = __float2half_rn(v0), h1 = __float2half_rn(v1);
                    __half l0 = __float2half_rn(v0 - __half2float(h0));
                    __half l1 = __float2half_rn(v1 - __half2float(h1));
                    *(__half2*)(Ch + o) = __halves2half2(h0, h1);
                    *(__half2*)(Cl + o) = __halves2half2(l0, l1);
                }
            }
        }
}

// ---------------- fp32 -> fp16 hi/lo split ----------------
__global__ __launch_bounds__(256)
void splitk(const float* __restrict__ in, __half* __restrict__ h, __half* __restrict__ l, int n)
{
    int i = (blockIdx.x * 256 + threadIdx.x) * 4;
    if (i >= n) return;
    float4 v = *(const float4*)(in + i);
    __half h0 = __float2half_rn(v.x), h1 = __float2half_rn(v.y);
    __half h2 = __float2half_rn(v.z), h3 = __float2half_rn(v.w);
    __half l0 = __float2half_rn(v.x - __half2float(h0));
    __half l1 = __float2half_rn(v.y - __half2float(h1));
    __half l2 = __float2half_rn(v.z - __half2float(h2));
    __half l3 = __float2half_rn(v.w - __half2float(h3));
    *(__half2*)(h + i)     = __halves2half2(h0, h1);
    *(__half2*)(h + i + 2) = __halves2half2(h2, h3);
    *(__half2*)(l + i)     = __halves2half2(l0, l1);
    *(__half2*)(l + i + 2) = __halves2half2(l2, l3);
}

// ---------------- transpose + split: x[R,C] -> xT hi/lo [C,R] ----------------
__global__ __launch_bounds__(256)
void tsplit(const float* __restrict__ in, __half* __restrict__ th, __half* __restrict__ tl,
            int R, int C)
{
    __shared__ float t[32][33];
    const int tx = threadIdx.x & 31, ty = threadIdx.x >> 5;
    const int c0 = blockIdx.x * 32, r0 = blockIdx.y * 32;
    #pragma unroll
    for (int i = 0; i < 32; i += 8)
        t[ty + i][tx] = in[(size_t)(r0 + ty + i) * C + c0 + tx];
    __syncthreads();
    #pragma unroll
    for (int i = 0; i < 32; i += 8) {
        float v = t[tx][ty + i];
        size_t o = (size_t)(c0 + ty + i) * R + r0 + tx;
        __half h = __float2half_rn(v);
        th[o] = h;
        tl[o] = __float2half_rn(v - __half2float(h));
    }
}

// ---------------- causal softmax: fp32 scores -> fp16 hi/lo attn ----------------
__device__ __forceinline__ float warpMax(float v) {
    #pragma unroll
    for (int o = 16; o; o >>= 1) v = fmaxf(v, __shfl_xor_sync(0xffffffffu, v, o));
    return v;
}
__device__ __forceinline__ float warpSum(float v) {
    #pragma unroll
    for (int o = 16; o; o >>= 1) v += __shfl_xor_sync(0xffffffffu, v, o);
    return v;
}

__global__ __launch_bounds__(256)
void causal_softmax(const float* __restrict__ S, __half* __restrict__ Ah,
                    __half* __restrict__ Al, int N)
{
    const int row = blockIdx.x;
    const int len = row + 1;
    const float* Srow = S + (size_t)row * N;
    const int tid = threadIdx.x;

    float vals[16];
    int cnt = 0;
    float m = -3.4e38f;
    for (int j = tid; j < len; j += 256) {
        float v = Srow[j];
        vals[cnt++] = v;
        m = fmaxf(m, v);
    }

    __shared__ float red[8];
    m = warpMax(m);
    if ((tid & 31) == 0) red[tid >> 5] = m;
    __syncthreads();
    float bm = red[0];
    #pragma unroll
    for (int w = 1; w < 8; w++) bm = fmaxf(bm, red[w]);
    __syncthreads();

    float sum = 0.f;
    for (int c = 0; c < cnt; c++) {
        float e = __expf(vals[c] - bm);
        vals[c] = e;
        sum += e;
    }
    sum = warpSum(sum);
    if ((tid & 31) == 0) red[tid >> 5] = sum;
    __syncthreads();
    float bs = 0.f;
    #pragma unroll
    for (int w = 0; w < 8; w++) bs += red[w];
    const float inv = 1.0f / bs;

    __half* ArH = Ah + (size_t)row * N;
    __half* ArL = Al + (size_t)row * N;
    cnt = 0;
    for (int j = tid; j < len; j += 256) {
        float w = vals[cnt++] * inv;
        __half h = __float2half_rn(w);
        ArH[j] = h;
        ArL[j] = __float2half_rn(w - __half2float(h));
    }
    const int zend = (len + 127) & ~127;     // zero to the 128 boundary for causal-K GEMM
    const __half z = __float2half_rn(0.0f);
    for (int j = len + tid; j < zend; j += 256) { ArH[j] = z; ArL[j] = z; }
}

// ---------------- host ----------------
extern "C" void kernel_launch(void* const* d_in, const int* in_sizes, int n_in,
                              void* d_out, int out_size)
{
    const float* x   = (const float*)d_in[0];
    const float* Wqk = (const float*)d_in[1];
    const float* Wov = (const float*)d_in[2];
    float* out = (float*)d_out;

    float* s;  cudaGetSymbolAddress((void**)&s, g_s);
    __half *xh, *xl, *xth, *xtl, *wqh, *wql, *wvh, *wvl, *qh, *ql, *ah, *al, *zh, *zl;
    cudaGetSymbolAddress((void**)&xh,  g_xh);  cudaGetSymbolAddress((void**)&xl,  g_xl);
    cudaGetSymbolAddress((void**)&xth, g_xth); cudaGetSymbolAddress((void**)&xtl, g_xtl);
    cudaGetSymbolAddress((void**)&wqh, g_wqh); cudaGetSymbolAddress((void**)&wql, g_wql);
    cudaGetSymbolAddress((void**)&wvh, g_wvh); cudaGetSymbolAddress((void**)&wvl, g_wvl);
    cudaGetSymbolAddress((void**)&qh,  g_qh);  cudaGetSymbolAddress((void**)&ql,  g_ql);
    cudaGetSymbolAddress((void**)&ah,  g_ah);  cudaGetSymbolAddress((void**)&al,  g_al);
    cudaGetSymbolAddress((void**)&zh,  g_zh);  cudaGetSymbolAddress((void**)&zl,  g_zl);

    cudaFuncSetAttribute(tgemm<true,  false, false>, cudaFuncAttributeMaxDynamicSharedMemorySize, SMEM_BYTES);
    cudaFuncSetAttribute(tgemm<false, true,  false>, cudaFuncAttributeMaxDynamicSharedMemorySize, SMEM_BYTES);
    cudaFuncSetAttribute(tgemm<true,  false, true >, cudaFuncAttributeMaxDynamicSharedMemorySize, SMEM_BYTES);
    cudaFuncSetAttribute(tgemm<false, false, false>, cudaFuncAttributeMaxDynamicSharedMemorySize, SMEM_BYTES);

    const int nx = NCTX * DMODEL, nw = DMODEL * DMODEL;

    splitk<<<nx / 1024, 256>>>(x,   xh,  xl,  nx);
    splitk<<<nw / 1024, 256>>>(Wqk, wqh, wql, nw);
    splitk<<<nw / 1024, 256>>>(Wov, wvh, wvl, nw);
    tsplit<<<dim3(DMODEL / 32, NCTX / 32), 256>>>(x, xth, xtl, NCTX, DMODEL);

    // 1) q = x @ Wqk^T  -> q hi/lo
    tgemm<true, false, false><<<dim3(DMODEL / BN, NCTX / BM), 256, SMEM_BYTES>>>(
        xh, xl, wqh, wql, nullptr, qh, ql, DMODEL, DMODEL, DMODEL, DMODEL);

    // 2) s = q @ x^T (causal block skip) -> fp32 scores
    tgemm<false, true, false><<<dim3(NCTX / BN, NCTX / BM), 256, SMEM_BYTES>>>(
        qh, ql, xh, xl, s, nullptr, nullptr, DMODEL, DMODEL, DMODEL, NCTX);

    // 3) softmax -> attn hi/lo (zero-filled to 128 boundary)
    causal_softmax<<<NCTX, 256>>>(s, ah, al, NCTX);

    // 4) z = attn @ x  (NT vs x^T, causal K limit) -> z hi/lo
    tgemm<true, false, true><<<dim3(DMODEL / BN, NCTX / BM), 256, SMEM_BYTES>>>(
        ah, al, xth, xtl, nullptr, zh, zl, NCTX, NCTX, NCTX, DMODEL);

    // 5) out = z @ Wov^T -> fp32 output
    tgemm<false, false, false><<<dim3(DMODEL / BN, NCTX / BM), 256, SMEM_BYTES>>>(
        zh, zl, wvh, wvl, out, nullptr, nullptr, DMODEL, DMODEL, DMODEL, DMODEL);
}

// round 4
// speedup vs baseline: 2.6470x; 1.0913x over previous
#include <cuda_runtime.h>
#include <cuda_fp16.h>
#include <cstdint>

#define NCTX 4096
#define DMODEL 2048

// ---------------- scratch (static device globals; no runtime alloc) ----------------
__device__ float g_s[(size_t)NCTX * NCTX];                        // 64 MB scores
__device__ __align__(256) __half g_xh[(size_t)NCTX * DMODEL];
__device__ __align__(256) __half g_xl[(size_t)NCTX * DMODEL];
__device__ __align__(256) __half g_xth[(size_t)DMODEL * NCTX];
__device__ __align__(256) __half g_xtl[(size_t)DMODEL * NCTX];
__device__ __align__(256) __half g_wqh[(size_t)DMODEL * DMODEL];
__device__ __align__(256) __half g_wql[(size_t)DMODEL * DMODEL];
__device__ __align__(256) __half g_wvh[(size_t)DMODEL * DMODEL];
__device__ __align__(256) __half g_wvl[(size_t)DMODEL * DMODEL];
__device__ __align__(256) __half g_qh[(size_t)NCTX * DMODEL];
__device__ __align__(256) __half g_ql[(size_t)NCTX * DMODEL];
__device__ __align__(256) __half g_ah[(size_t)NCTX * NCTX];
__device__ __align__(256) __half g_al[(size_t)NCTX * NCTX];
__device__ __align__(256) __half g_zh[(size_t)NCTX * DMODEL];
__device__ __align__(256) __half g_zl[(size_t)NCTX * DMODEL];

// ---------------- GEMM config ----------------
constexpr int BM = 128, BN = 128, BK = 32;
constexpr int TILE_B = BM * BK * 2;                 // 8192 B per matrix tile
constexpr int STAGE  = 4 * TILE_B;                  // Ah,Al,Bh,Bl = 32 KB
constexpr int NSTAGE = 3;
constexpr int SMEM_BYTES = NSTAGE * STAGE;          // 96 KB

__device__ __forceinline__ uint32_t sm_addr(const void* p) {
    uint32_t a;
    asm("{ .reg .u64 t; cvta.to.shared.u64 t, %1; cvt.u32.u64 %0, t; }" : "=r"(a) : "l"(p));
    return a;
}
__device__ __forceinline__ void cpasync16(uint32_t s, const void* g) {
    asm volatile("cp.async.cg.shared.global [%0], [%1], 16;" :: "r"(s), "l"(g));
}
__device__ __forceinline__ void ldmx4(uint32_t& r0, uint32_t& r1, uint32_t& r2, uint32_t& r3,
                                      uint32_t a) {
    asm volatile("ldmatrix.sync.aligned.m8n8.x4.shared.b16 {%0,%1,%2,%3}, [%4];"
                 : "=r"(r0), "=r"(r1), "=r"(r2), "=r"(r3) : "r"(a));
}
__device__ __forceinline__ void mma16816(float* c, const uint32_t* a, const uint32_t* b) {
    asm volatile("mma.sync.aligned.m16n8k16.row.col.f32.f16.f16.f32 "
                 "{%0,%1,%2,%3}, {%4,%5,%6,%7}, {%8,%9}, {%0,%1,%2,%3};"
                 : "+f"(c[0]), "+f"(c[1]), "+f"(c[2]), "+f"(c[3])
                 : "r"(a[0]), "r"(a[1]), "r"(a[2]), "r"(a[3]), "r"(b[0]), "r"(b[1]));
}
// swizzled byte offset for (row, 16B-chunk j) in a 64B-per-row tile
__device__ __forceinline__ uint32_t swoff(int row, int j) {
    return row * 64 + ((j ^ ((row >> 1) & 3)) << 4);
}

// ---------------- split-precision fp16 NT GEMM via mma.sync ----------------
// C[M,N] = (Ah[+Al]) * (Bh+Bl)^T, fp32 accumulate.
// NPASS==3: hh + hl + lh (full split precision).  NPASS==2: hh + hl (A_lo unused).
template<int NPASS, bool SPLIT_OUT, bool CSKIP, bool CK>
__global__ __launch_bounds__(256, 1)
void tgemm(const __half* __restrict__ Ah, const __half* __restrict__ Al,
           const __half* __restrict__ Bh, const __half* __restrict__ Bl,
           float* __restrict__ Cf, __half* __restrict__ Ch, __half* __restrict__ Cl,
           int K, int lda, int ldb, int ldc)
{
    const int bx = blockIdx.x, by = blockIdx.y;
    if (CSKIP && bx > by) return;                    // BM == BN == 128
    const int Keff = CK ? min(K, (by + 1) * BM) : K;
    const int nC = Keff / BK;

    extern __shared__ __align__(1024) char smem[];
    const uint32_t sb = sm_addr(smem);

    const int tid = threadIdx.x;
    const int lane = tid & 31, wid = tid >> 5;
    const int wm = wid & 1, wn = wid >> 1;           // warp grid 2(M) x 4(N)

    const int lrow = tid >> 1;                       // 0..127
    const int ljb  = (tid & 1) * 2;                  // chunk base 0 or 2
    const size_t arow = (size_t)(by * BM + lrow) * lda;
    const size_t brow = (size_t)(bx * BN + lrow) * ldb;

    float acc[4][4][4];
    #pragma unroll
    for (int i = 0; i < 4; i++)
        #pragma unroll
        for (int j = 0; j < 4; j++)
            #pragma unroll
            for (int r = 0; r < 4; r++) acc[i][j][r] = 0.f;

    auto issue = [&](int c) {
        const uint32_t s0 = sb + (c % NSTAGE) * STAGE;
        const int kc = c * BK;
        #pragma unroll
        for (int jj = 0; jj < 2; jj++) {
            const int j = ljb + jj;
            const uint32_t so = swoff(lrow, j);
            const size_t ga = arow + kc + j * 8;
            const size_t gb = brow + kc + j * 8;
            cpasync16(s0 + so, Ah + ga);
            if (NPASS == 3) cpasync16(s0 + TILE_B + so, Al + ga);
            cpasync16(s0 + 2 * TILE_B + so, Bh + gb);
            cpasync16(s0 + 3 * TILE_B + so, Bl + gb);
        }
    };

    issue(0); asm volatile("cp.async.commit_group;");
    issue(1); asm volatile("cp.async.commit_group;");

    for (int c = 0; c < nC; c++) {
        asm volatile("cp.async.wait_group 1;");
        __syncthreads();
        // prefetch stage c+2 into buffer (c-1)%NSTAGE (all warps finished it at the sync)
        if (c + 2 < nC) issue(c + 2);
        asm volatile("cp.async.commit_group;");

        const uint32_t s0 = sb + (c % NSTAGE) * STAGE;
        #pragma unroll
        for (int ks = 0; ks < 2; ks++) {
            uint32_t a_h[4][4], a_l[4][4], b_h[4][2], b_l[4][2];
            #pragma unroll
            for (int i = 0; i < 4; i++) {
                const int row = wm * 64 + i * 16 + (lane & 15);
                const int ch  = 2 * ks + (lane >> 4);
                const uint32_t off = swoff(row, ch);
                ldmx4(a_h[i][0], a_h[i][1], a_h[i][2], a_h[i][3], s0 + off);
                if (NPASS == 3)
                    ldmx4(a_l[i][0], a_l[i][1], a_l[i][2], a_l[i][3], s0 + TILE_B + off);
            }
            #pragma unroll
            for (int p = 0; p < 2; p++) {
                const int row = wn * 32 + p * 16 + (lane & 7) + ((lane & 16) >> 1);
                const int ch  = 2 * ks + ((lane >> 3) & 1);
                const uint32_t off = swoff(row, ch);
                uint32_t r0, r1, r2, r3;
                ldmx4(r0, r1, r2, r3, s0 + 2 * TILE_B + off);
                b_h[2 * p][0] = r0; b_h[2 * p][1] = r1;
                b_h[2 * p + 1][0] = r2; b_h[2 * p + 1][1] = r3;
                ldmx4(r0, r1, r2, r3, s0 + 3 * TILE_B + off);
                b_l[2 * p][0] = r0; b_l[2 * p][1] = r1;
                b_l[2 * p + 1][0] = r2; b_l[2 * p + 1][1] = r3;
            }
            #pragma unroll
            for (int i = 0; i < 4; i++)
                #pragma unroll
                for (int j = 0; j < 4; j++) {
                    mma16816(acc[i][j], a_h[i], b_h[j]);
                    mma16816(acc[i][j], a_h[i], b_l[j]);
                    if (NPASS == 3) mma16816(acc[i][j], a_l[i], b_h[j]);
                }
        }
        __syncthreads();
    }

    // ---------------- epilogue ----------------
    const int r0 = by * BM + wm * 64 + (lane >> 2);
    const int c0 = bx * BN + wn * 32 + (lane & 3) * 2;
    #pragma unroll
    for (int i = 0; i < 4; i++)
        #pragma unroll
        for (int j = 0; j < 4; j++) {
            const int rr = r0 + i * 16;
            const int cc = c0 + j * 8;
            #pragma unroll
            for (int h = 0; h < 2; h++) {
                const float v0 = acc[i][j][2 * h], v1 = acc[i][j][2 * h + 1];
                const size_t o = (size_t)(rr + 8 * h) * ldc + cc;
                if (!SPLIT_OUT) {
                    *(float2*)(Cf + o) = make_float2(v0, v1);
                } else {
                    __half h0 = __float2half_rn(v0), h1 = __float2half_rn(v1);
                    __half l0 = __float2half_rn(v0 - __half2float(h0));
                    __half l1 = __float2half_rn(v1 - __half2float(h1));
                    *(__half2*)(Ch + o) = __halves2half2(h0, h1);
                    *(__half2*)(Cl + o) = __halves2half2(l0, l1);
                }
            }
        }
}

// ---------------- fp32 -> fp16 hi/lo split ----------------
__global__ __launch_bounds__(256)
void splitk(const float* __restrict__ in, __half* __restrict__ h, __half* __restrict__ l, int n)
{
    int i = (blockIdx.x * 256 + threadIdx.x) * 4;
    if (i >= n) return;
    float4 v = *(const float4*)(in + i);
    __half h0 = __float2half_rn(v.x), h1 = __float2half_rn(v.y);
    __half h2 = __float2half_rn(v.z), h3 = __float2half_rn(v.w);
    __half l0 = __float2half_rn(v.x - __half2float(h0));
    __half l1 = __float2half_rn(v.y - __half2float(h1));
    __half l2 = __float2half_rn(v.z - __half2float(h2));
    __half l3 = __float2half_rn(v.w - __half2float(h3));
    *(__half2*)(h + i)     = __halves2half2(h0, h1);
    *(__half2*)(h + i + 2) = __halves2half2(h2, h3);
    *(__half2*)(l + i)     = __halves2half2(l0, l1);
    *(__half2*)(l + i + 2) = __halves2half2(l2, l3);
}

// ---------------- transpose + split: x[R,C] -> xT hi/lo [C,R] ----------------
__global__ __launch_bounds__(256)
void tsplit(const float* __restrict__ in, __half* __restrict__ th, __half* __restrict__ tl,
            int R, int C)
{
    __shared__ float t[32][33];
    const int tx = threadIdx.x & 31, ty = threadIdx.x >> 5;
    const int c0 = blockIdx.x * 32, r0 = blockIdx.y * 32;
    #pragma unroll
    for (int i = 0; i < 32; i += 8)
        t[ty + i][tx] = in[(size_t)(r0 + ty + i) * C + c0 + tx];
    __syncthreads();
    #pragma unroll
    for (int i = 0; i < 32; i += 8) {
        float v = t[tx][ty + i];
        size_t o = (size_t)(c0 + ty + i) * R + r0 + tx;
        __half h = __float2half_rn(v);
        th[o] = h;
        tl[o] = __float2half_rn(v - __half2float(h));
    }
}

// ---------------- causal softmax: fp32 scores -> fp16 hi/lo attn ----------------
__device__ __forceinline__ float warpMax(float v) {
    #pragma unroll
    for (int o = 16; o; o >>= 1) v = fmaxf(v, __shfl_xor_sync(0xffffffffu, v, o));
    return v;
}
__device__ __forceinline__ float warpSum(float v) {
    #pragma unroll
    for (int o = 16; o; o >>= 1) v += __shfl_xor_sync(0xffffffffu, v, o);
    return v;
}

__global__ __launch_bounds__(256)
void causal_softmax(const float* __restrict__ S, __half* __restrict__ Ah,
                    __half* __restrict__ Al, int N)
{
    const int row = blockIdx.x;
    const int len = row + 1;
    const float* Srow = S + (size_t)row * N;
    const int tid = threadIdx.x;

    float vals[16];
    int cnt = 0;
    float m = -3.4e38f;
    for (int j = tid; j < len; j += 256) {
        float v = Srow[j];
        vals[cnt++] = v;
        m = fmaxf(m, v);
    }

    __shared__ float red[8];
    m = warpMax(m);
    if ((tid & 31) == 0) red[tid >> 5] = m;
    __syncthreads();
    float bm = red[0];
    #pragma unroll
    for (int w = 1; w < 8; w++) bm = fmaxf(bm, red[w]);
    __syncthreads();

    float sum = 0.f;
    for (int c = 0; c < cnt; c++) {
        float e = __expf(vals[c] - bm);
        vals[c] = e;
        sum += e;
    }
    sum = warpSum(sum);
    if ((tid & 31) == 0) red[tid >> 5] = sum;
    __syncthreads();
    float bs = 0.f;
    #pragma unroll
    for (int w = 0; w < 8; w++) bs += red[w];
    const float inv = 1.0f / bs;

    __half* ArH = Ah + (size_t)row * N;
    __half* ArL = Al + (size_t)row * N;
    cnt = 0;
    for (int j = tid; j < len; j += 256) {
        float w = vals[cnt++] * inv;
        __half h = __float2half_rn(w);
        ArH[j] = h;
        ArL[j] = __float2half_rn(w - __half2float(h));
    }
    const int zend = (len + 127) & ~127;
    const __half z = __float2half_rn(0.0f);
    for (int j = len + tid; j < zend; j += 256) { ArH[j] = z; ArL[j] = z; }
}

// ---------------- host ----------------
extern "C" void kernel_launch(void* const* d_in, const int* in_sizes, int n_in,
                              void* d_out, int out_size)
{
    const float* x   = (const float*)d_in[0];
    const float* Wqk = (const float*)d_in[1];
    const float* Wov = (const float*)d_in[2];
    float* out = (float*)d_out;

    float* s;  cudaGetSymbolAddress((void**)&s, g_s);
    __half *xh, *xl, *xth, *xtl, *wqh, *wql, *wvh, *wvl, *qh, *ql, *ah, *al, *zh, *zl;
    cudaGetSymbolAddress((void**)&xh,  g_xh);  cudaGetSymbolAddress((void**)&xl,  g_xl);
    cudaGetSymbolAddress((void**)&xth, g_xth); cudaGetSymbolAddress((void**)&xtl, g_xtl);
    cudaGetSymbolAddress((void**)&wqh, g_wqh); cudaGetSymbolAddress((void**)&wql, g_wql);
    cudaGetSymbolAddress((void**)&wvh, g_wvh); cudaGetSymbolAddress((void**)&wvl, g_wvl);
    cudaGetSymbolAddress((void**)&qh,  g_qh);  cudaGetSymbolAddress((void**)&ql,  g_ql);
    cudaGetSymbolAddress((void**)&ah,  g_ah);  cudaGetSymbolAddress((void**)&al,  g_al);
    cudaGetSymbolAddress((void**)&zh,  g_zh);  cudaGetSymbolAddress((void**)&zl,  g_zl);

    cudaFuncSetAttribute(tgemm<3, true,  false, false>, cudaFuncAttributeMaxDynamicSharedMemorySize, SMEM_BYTES);
    cudaFuncSetAttribute(tgemm<3, false, true,  false>, cudaFuncAttributeMaxDynamicSharedMemorySize, SMEM_BYTES);
    cudaFuncSetAttribute(tgemm<2, true,  false, true >, cudaFuncAttributeMaxDynamicSharedMemorySize, SMEM_BYTES);
    cudaFuncSetAttribute(tgemm<2, false, false, false>, cudaFuncAttributeMaxDynamicSharedMemorySize, SMEM_BYTES);

    const int nx = NCTX * DMODEL, nw = DMODEL * DMODEL;

    splitk<<<nx / 1024, 256>>>(x,   xh,  xl,  nx);
    splitk<<<nw / 1024, 256>>>(Wqk, wqh, wql, nw);
    splitk<<<nw / 1024, 256>>>(Wov, wvh, wvl, nw);
    tsplit<<<dim3(DMODEL / 32, NCTX / 32), 256>>>(x, xth, xtl, NCTX, DMODEL);

    // 1) q = x @ Wqk^T  -> q hi/lo (full 3-pass precision; feeds scores)
    tgemm<3, true, false, false><<<dim3(DMODEL / BN, NCTX / BM), 256, SMEM_BYTES>>>(
        xh, xl, wqh, wql, nullptr, qh, ql, DMODEL, DMODEL, DMODEL, DMODEL);

    // 2) s = q @ x^T (causal block skip) -> fp32 scores (full 3-pass precision)
    tgemm<3, false, true, false><<<dim3(NCTX / BN, NCTX / BM), 256, SMEM_BYTES>>>(
        qh, ql, xh, xl, s, nullptr, nullptr, DMODEL, DMODEL, DMODEL, NCTX);

    // 3) softmax -> attn hi/lo (zero-filled to 128 boundary)
    causal_softmax<<<NCTX, 256>>>(s, ah, al, NCTX);

    // 4) z = attn @ x (NT vs x^T, causal K limit) -> z hi/lo (2-pass; post-softmax)
    tgemm<2, true, false, true><<<dim3(DMODEL / BN, NCTX / BM), 256, SMEM_BYTES>>>(
        ah, al, xth, xtl, nullptr, zh, zl, NCTX, NCTX, NCTX, DMODEL);

    // 5) out = z @ Wov^T -> fp32 output (2-pass)
    tgemm<2, false, false, false><<<dim3(DMODEL / BN, NCTX / BM), 256, SMEM_BYTES>>>(
        zh, zl, wvh, wvl, out, nullptr, nullptr, DMODEL, DMODEL, DMODEL, DMODEL);
}

// round 5
// speedup vs baseline: 3.3553x; 1.2676x over previous
#include <cuda_runtime.h>
#include <cuda_fp16.h>
#include <cstdint>

#define NCTX 4096
#define DMODEL 2048

// ---------------- scratch (static device globals; no runtime alloc) ----------------
__device__ float g_s[(size_t)NCTX * NCTX];                        // 64 MB scores
__device__ __align__(256) __half g_xh[(size_t)NCTX * DMODEL];
__device__ __align__(256) __half g_xl[(size_t)NCTX * DMODEL];
__device__ __align__(256) __half g_wqh[(size_t)DMODEL * DMODEL];
__device__ __align__(256) __half g_wql[(size_t)DMODEL * DMODEL];
__device__ __align__(256) __half g_wvh[(size_t)DMODEL * DMODEL];
__device__ __align__(256) __half g_wvl[(size_t)DMODEL * DMODEL];
__device__ __align__(256) __half g_qh[(size_t)NCTX * DMODEL];
__device__ __align__(256) __half g_ql[(size_t)NCTX * DMODEL];
__device__ __align__(256) __half g_zh[(size_t)NCTX * DMODEL];
__device__ __align__(256) __half g_zl[(size_t)NCTX * DMODEL];
// sparse attention weights (full 4096/row worst case -> always correct)
__device__ uint32_t g_widx[(size_t)NCTX * NCTX];                  // 64 MB
__device__ float    g_wval[(size_t)NCTX * NCTX];                  // 64 MB
__device__ int      g_cnt[NCTX];

// ---------------- GEMM config ----------------
constexpr int BM = 128, BN = 128, BK = 32;
constexpr int TILE_B = BM * BK * 2;                 // 8192 B per matrix tile
constexpr int STAGE  = 4 * TILE_B;                  // Ah,Al,Bh,Bl = 32 KB
constexpr int NSTAGE = 3;
constexpr int SMEM_BYTES = NSTAGE * STAGE;          // 96 KB

__device__ __forceinline__ uint32_t sm_addr(const void* p) {
    uint32_t a;
    asm("{ .reg .u64 t; cvta.to.shared.u64 t, %1; cvt.u32.u64 %0, t; }" : "=r"(a) : "l"(p));
    return a;
}
__device__ __forceinline__ void cpasync16(uint32_t s, const void* g) {
    asm volatile("cp.async.cg.shared.global [%0], [%1], 16;" :: "r"(s), "l"(g));
}
__device__ __forceinline__ void ldmx4(uint32_t& r0, uint32_t& r1, uint32_t& r2, uint32_t& r3,
                                      uint32_t a) {
    asm volatile("ldmatrix.sync.aligned.m8n8.x4.shared.b16 {%0,%1,%2,%3}, [%4];"
                 : "=r"(r0), "=r"(r1), "=r"(r2), "=r"(r3) : "r"(a));
}
__device__ __forceinline__ void mma16816(float* c, const uint32_t* a, const uint32_t* b) {
    asm volatile("mma.sync.aligned.m16n8k16.row.col.f32.f16.f16.f32 "
                 "{%0,%1,%2,%3}, {%4,%5,%6,%7}, {%8,%9}, {%0,%1,%2,%3};"
                 : "+f"(c[0]), "+f"(c[1]), "+f"(c[2]), "+f"(c[3])
                 : "r"(a[0]), "r"(a[1]), "r"(a[2]), "r"(a[3]), "r"(b[0]), "r"(b[1]));
}
__device__ __forceinline__ uint32_t swoff(int row, int j) {
    return row * 64 + ((j ^ ((row >> 1) & 3)) << 4);
}

// ---------------- split-precision fp16 NT GEMM via mma.sync ----------------
template<int NPASS, bool SPLIT_OUT, bool CSKIP, bool CK>
__global__ __launch_bounds__(256, 1)
void tgemm(const __half* __restrict__ Ah, const __half* __restrict__ Al,
           const __half* __restrict__ Bh, const __half* __restrict__ Bl,
           float* __restrict__ Cf, __half* __restrict__ Ch, __half* __restrict__ Cl,
           int K, int lda, int ldb, int ldc)
{
    const int bx = blockIdx.x, by = blockIdx.y;
    if (CSKIP && bx > by) return;
    const int Keff = CK ? min(K, (by + 1) * BM) : K;
    const int nC = Keff / BK;

    extern __shared__ __align__(1024) char smem[];
    const uint32_t sb = sm_addr(smem);

    const int tid = threadIdx.x;
    const int lane = tid & 31, wid = tid >> 5;
    const int wm = wid & 1, wn = wid >> 1;

    const int lrow = tid >> 1;
    const int ljb  = (tid & 1) * 2;
    const size_t arow = (size_t)(by * BM + lrow) * lda;
    const size_t brow = (size_t)(bx * BN + lrow) * ldb;

    float acc[4][4][4];
    #pragma unroll
    for (int i = 0; i < 4; i++)
        #pragma unroll
        for (int j = 0; j < 4; j++)
            #pragma unroll
            for (int r = 0; r < 4; r++) acc[i][j][r] = 0.f;

    auto issue = [&](int c) {
        const uint32_t s0 = sb + (c % NSTAGE) * STAGE;
        const int kc = c * BK;
        #pragma unroll
        for (int jj = 0; jj < 2; jj++) {
            const int j = ljb + jj;
            const uint32_t so = swoff(lrow, j);
            const size_t ga = arow + kc + j * 8;
            const size_t gb = brow + kc + j * 8;
            cpasync16(s0 + so, Ah + ga);
            if (NPASS == 3) cpasync16(s0 + TILE_B + so, Al + ga);
            cpasync16(s0 + 2 * TILE_B + so, Bh + gb);
            cpasync16(s0 + 3 * TILE_B + so, Bl + gb);
        }
    };

    issue(0); asm volatile("cp.async.commit_group;");
    issue(1); asm volatile("cp.async.commit_group;");

    for (int c = 0; c < nC; c++) {
        asm volatile("cp.async.wait_group 1;");
        __syncthreads();
        if (c + 2 < nC) issue(c + 2);
        asm volatile("cp.async.commit_group;");

        const uint32_t s0 = sb + (c % NSTAGE) * STAGE;
        #pragma unroll
        for (int ks = 0; ks < 2; ks++) {
            uint32_t a_h[4][4], a_l[4][4], b_h[4][2], b_l[4][2];
            #pragma unroll
            for (int i = 0; i < 4; i++) {
                const int row = wm * 64 + i * 16 + (lane & 15);
                const int ch  = 2 * ks + (lane >> 4);
                const uint32_t off = swoff(row, ch);
                ldmx4(a_h[i][0], a_h[i][1], a_h[i][2], a_h[i][3], s0 + off);
                if (NPASS == 3)
                    ldmx4(a_l[i][0], a_l[i][1], a_l[i][2], a_l[i][3], s0 + TILE_B + off);
            }
            #pragma unroll
            for (int p = 0; p < 2; p++) {
                const int row = wn * 32 + p * 16 + (lane & 7) + ((lane & 16) >> 1);
                const int ch  = 2 * ks + ((lane >> 3) & 1);
                const uint32_t off = swoff(row, ch);
                uint32_t r0, r1, r2, r3;
                ldmx4(r0, r1, r2, r3, s0 + 2 * TILE_B + off);
                b_h[2 * p][0] = r0; b_h[2 * p][1] = r1;
                b_h[2 * p + 1][0] = r2; b_h[2 * p + 1][1] = r3;
                ldmx4(r0, r1, r2, r3, s0 + 3 * TILE_B + off);
                b_l[2 * p][0] = r0; b_l[2 * p][1] = r1;
                b_l[2 * p + 1][0] = r2; b_l[2 * p + 1][1] = r3;
            }
            #pragma unroll
            for (int i = 0; i < 4; i++)
                #pragma unroll
                for (int j = 0; j < 4; j++) {
                    mma16816(acc[i][j], a_h[i], b_h[j]);
                    mma16816(acc[i][j], a_h[i], b_l[j]);
                    if (NPASS == 3) mma16816(acc[i][j], a_l[i], b_h[j]);
                }
        }
        __syncthreads();
    }

    const int r0 = by * BM + wm * 64 + (lane >> 2);
    const int c0 = bx * BN + wn * 32 + (lane & 3) * 2;
    #pragma unroll
    for (int i = 0; i < 4; i++)
        #pragma unroll
        for (int j = 0; j < 4; j++) {
            const int rr = r0 + i * 16;
            const int cc = c0 + j * 8;
            #pragma unroll
            for (int h = 0; h < 2; h++) {
                const float v0 = acc[i][j][2 * h], v1 = acc[i][j][2 * h + 1];
                const size_t o = (size_t)(rr + 8 * h) * ldc + cc;
                if (!SPLIT_OUT) {
                    *(float2*)(Cf + o) = make_float2(v0, v1);
                } else {
                    __half h0 = __float2half_rn(v0), h1 = __float2half_rn(v1);
                    __half l0 = __float2half_rn(v0 - __half2float(h0));
                    __half l1 = __float2half_rn(v1 - __half2float(h1));
                    *(__half2*)(Ch + o) = __halves2half2(h0, h1);
                    *(__half2*)(Cl + o) = __halves2half2(l0, l1);
                }
            }
        }
}

// ---------------- fp32 -> fp16 hi/lo split ----------------
__global__ __launch_bounds__(256)
void splitk(const float* __restrict__ in, __half* __restrict__ h, __half* __restrict__ l, int n)
{
    int i = (blockIdx.x * 256 + threadIdx.x) * 4;
    if (i >= n) return;
    float4 v = *(const float4*)(in + i);
    __half h0 = __float2half_rn(v.x), h1 = __float2half_rn(v.y);
    __half h2 = __float2half_rn(v.z), h3 = __float2half_rn(v.w);
    __half l0 = __float2half_rn(v.x - __half2float(h0));
    __half l1 = __float2half_rn(v.y - __half2float(h1));
    __half l2 = __float2half_rn(v.z - __half2float(h2));
    __half l3 = __float2half_rn(v.w - __half2float(h3));
    *(__half2*)(h + i)     = __halves2half2(h0, h1);
    *(__half2*)(h + i + 2) = __halves2half2(h2, h3);
    *(__half2*)(l + i)     = __halves2half2(l0, l1);
    *(__half2*)(l + i + 2) = __halves2half2(l2, l3);
}

// ---------------- causal softmax -> sparse (idx, weight) lists ----------------
__device__ __forceinline__ float warpMax(float v) {
    #pragma unroll
    for (int o = 16; o; o >>= 1) v = fmaxf(v, __shfl_xor_sync(0xffffffffu, v, o));
    return v;
}
__device__ __forceinline__ float warpSum(float v) {
    #pragma unroll
    for (int o = 16; o; o >>= 1) v += __shfl_xor_sync(0xffffffffu, v, o);
    return v;
}

// Keep weights with unnormalized exp > e^-18 (~1.52e-8). Z sums ALL terms, so
// retained weights are exact; dropped mass <= 4096 * e^-18 / Z ~ 4e-5.
__global__ __launch_bounds__(256)
void causal_softmax_sparse(const float* __restrict__ S, uint32_t* __restrict__ Widx,
                           float* __restrict__ Wval, int* __restrict__ Cnt, int N)
{
    const int row = blockIdx.x;
    const int len = row + 1;
    const float* Srow = S + (size_t)row * N;
    const int tid = threadIdx.x;

    __shared__ float red[8];
    __shared__ int scnt;
    if (tid == 0) scnt = 0;

    float vals[16];
    int cnt = 0;
    float m = -3.4e38f;
    for (int j = tid; j < len; j += 256) {
        float v = Srow[j];
        vals[cnt++] = v;
        m = fmaxf(m, v);
    }

    m = warpMax(m);
    if ((tid & 31) == 0) red[tid >> 5] = m;
    __syncthreads();
    float bm = red[0];
    #pragma unroll
    for (int w = 1; w < 8; w++) bm = fmaxf(bm, red[w]);
    __syncthreads();

    float sum = 0.f;
    for (int c = 0; c < cnt; c++) {
        float e = __expf(vals[c] - bm);
        vals[c] = e;
        sum += e;
    }
    sum = warpSum(sum);
    if ((tid & 31) == 0) red[tid >> 5] = sum;
    __syncthreads();
    float bs = 0.f;
    #pragma unroll
    for (int w = 0; w < 8; w++) bs += red[w];
    const float inv = 1.0f / bs;

    uint32_t* Wi = Widx + (size_t)row * N;
    float*    Wv = Wval + (size_t)row * N;
    for (int c = 0; c < cnt; c++) {
        const float e = vals[c];
        if (e > 1.523e-8f) {
            const int slot = atomicAdd(&scnt, 1);
            Wi[slot] = tid + c * 256;
            Wv[slot] = e * inv;
        }
    }
    __syncthreads();
    if (tid == 0) Cnt[row] = scnt;
}

// ---------------- sparse z = attn @ x (fp32), emit z hi/lo ----------------
__global__ __launch_bounds__(256)
void sparse_av(const float* __restrict__ x, const uint32_t* __restrict__ Widx,
               const float* __restrict__ Wval, const int* __restrict__ Cnt,
               __half* __restrict__ Zh, __half* __restrict__ Zl)
{
    const int row = blockIdx.x;
    const int c = Cnt[row];
    const int tid = threadIdx.x;

    __shared__ float sw[256];
    __shared__ uint32_t sj[256];

    float acc[8];
    #pragma unroll
    for (int r = 0; r < 8; r++) acc[r] = 0.f;

    const uint32_t* Wi = Widx + (size_t)row * NCTX;
    const float*    Wv = Wval + (size_t)row * NCTX;

    for (int base = 0; base < c; base += 256) {
        const int m = min(256, c - base);
        __syncthreads();
        if (tid < m) { sw[tid] = Wv[base + tid]; sj[tid] = Wi[base + tid]; }
        __syncthreads();
        for (int p = 0; p < m; p++) {
            const float w = sw[p];
            const float* xr = x + (size_t)sj[p] * DMODEL + tid * 8;
            const float4 a = *(const float4*)xr;
            const float4 b = *(const float4*)(xr + 4);
            acc[0] = fmaf(w, a.x, acc[0]); acc[1] = fmaf(w, a.y, acc[1]);
            acc[2] = fmaf(w, a.z, acc[2]); acc[3] = fmaf(w, a.w, acc[3]);
            acc[4] = fmaf(w, b.x, acc[4]); acc[5] = fmaf(w, b.y, acc[5]);
            acc[6] = fmaf(w, b.z, acc[6]); acc[7] = fmaf(w, b.w, acc[7]);
        }
    }

    __half* zh = Zh + (size_t)row * DMODEL + tid * 8;
    __half* zl = Zl + (size_t)row * DMODEL + tid * 8;
    #pragma unroll
    for (int r = 0; r < 8; r += 2) {
        __half h0 = __float2half_rn(acc[r]),     h1 = __float2half_rn(acc[r + 1]);
        __half l0 = __float2half_rn(acc[r] - __half2float(h0));
        __half l1 = __float2half_rn(acc[r + 1] - __half2float(h1));
        *(__half2*)(zh + r) = __halves2half2(h0, h1);
        *(__half2*)(zl + r) = __halves2half2(l0, l1);
    }
}

// ---------------- host ----------------
extern "C" void kernel_launch(void* const* d_in, const int* in_sizes, int n_in,
                              void* d_out, int out_size)
{
    const float* x   = (const float*)d_in[0];
    const float* Wqk = (const float*)d_in[1];
    const float* Wov = (const float*)d_in[2];
    float* out = (float*)d_out;

    float* s;  cudaGetSymbolAddress((void**)&s, g_s);
    __half *xh, *xl, *wqh, *wql, *wvh, *wvl, *qh, *ql, *zh, *zl;
    uint32_t* widx; float* wval; int* cnt;
    cudaGetSymbolAddress((void**)&xh,  g_xh);  cudaGetSymbolAddress((void**)&xl,  g_xl);
    cudaGetSymbolAddress((void**)&wqh, g_wqh); cudaGetSymbolAddress((void**)&wql, g_wql);
    cudaGetSymbolAddress((void**)&wvh, g_wvh); cudaGetSymbolAddress((void**)&wvl, g_wvl);
    cudaGetSymbolAddress((void**)&qh,  g_qh);  cudaGetSymbolAddress((void**)&ql,  g_ql);
    cudaGetSymbolAddress((void**)&zh,  g_zh);  cudaGetSymbolAddress((void**)&zl,  g_zl);
    cudaGetSymbolAddress((void**)&widx, g_widx);
    cudaGetSymbolAddress((void**)&wval, g_wval);
    cudaGetSymbolAddress((void**)&cnt,  g_cnt);

    cudaFuncSetAttribute(tgemm<3, true,  false, false>, cudaFuncAttributeMaxDynamicSharedMemorySize, SMEM_BYTES);
    cudaFuncSetAttribute(tgemm<3, false, true,  false>, cudaFuncAttributeMaxDynamicSharedMemorySize, SMEM_BYTES);
    cudaFuncSetAttribute(tgemm<2, false, false, false>, cudaFuncAttributeMaxDynamicSharedMemorySize, SMEM_BYTES);

    const int nx = NCTX * DMODEL, nw = DMODEL * DMODEL;

    splitk<<<nx / 1024, 256>>>(x,   xh,  xl,  nx);
    splitk<<<nw / 1024, 256>>>(Wqk, wqh, wql, nw);
    splitk<<<nw / 1024, 256>>>(Wov, wvh, wvl, nw);

    // 1) q = x @ Wqk^T  -> q hi/lo (3-pass; feeds scores)
    tgemm<3, true, false, false><<<dim3(DMODEL / BN, NCTX / BM), 256, SMEM_BYTES>>>(
        xh, xl, wqh, wql, nullptr, qh, ql, DMODEL, DMODEL, DMODEL, DMODEL);

    // 2) s = q @ x^T (causal block skip) -> fp32 scores (3-pass)
    tgemm<3, false, true, false><<<dim3(NCTX / BN, NCTX / BM), 256, SMEM_BYTES>>>(
        qh, ql, xh, xl, s, nullptr, nullptr, DMODEL, DMODEL, DMODEL, NCTX);

    // 3) softmax -> sparse (idx, weight) lists
    causal_softmax_sparse<<<NCTX, 256>>>(s, widx, wval, cnt, NCTX);

    // 4) z = attn @ x via sparse gather (fp32 exact) -> z hi/lo
    sparse_av<<<NCTX, 256>>>(x, widx, wval, cnt, zh, zl);

    // 5) out = z @ Wov^T -> fp32 output (2-pass)
    tgemm<2, false, false, false><<<dim3(DMODEL / BN, NCTX / BM), 256, SMEM_BYTES>>>(
        zh, zl, wvh, wvl, out, nullptr, nullptr, DMODEL, DMODEL, DMODEL, DMODEL);
}

// round 6
// speedup vs baseline: 3.7562x; 1.1195x over previous
#include <cuda_runtime.h>
#include <cuda_fp16.h>
#include <cstdint>

#define NCTX 4096
#define DMODEL 2048

// ---------------- scratch (static device globals; no runtime alloc) ----------------
__device__ float g_s[(size_t)NCTX * NCTX];                        // 64 MB scores
__device__ __align__(256) __half g_xh[(size_t)NCTX * DMODEL];
__device__ __align__(256) __half g_xl[(size_t)NCTX * DMODEL];
__device__ __align__(256) __half g_wqh[(size_t)DMODEL * DMODEL];
__device__ __align__(256) __half g_wql[(size_t)DMODEL * DMODEL];
__device__ __align__(256) __half g_wvh[(size_t)DMODEL * DMODEL];
__device__ __align__(256) __half g_wvl[(size_t)DMODEL * DMODEL];
__device__ __align__(256) __half g_qh[(size_t)NCTX * DMODEL];
__device__ __align__(256) __half g_ql[(size_t)NCTX * DMODEL];
__device__ __align__(256) __half g_zh[(size_t)NCTX * DMODEL];
__device__ __align__(256) __half g_zl[(size_t)NCTX * DMODEL];
// sparse attention weights (full 4096/row worst case -> always correct)
__device__ uint32_t g_widx[(size_t)NCTX * NCTX];                  // 64 MB
__device__ float    g_wval[(size_t)NCTX * NCTX];                  // 64 MB
__device__ int      g_cnt[NCTX];

// ---------------- GEMM config ----------------
constexpr int BM = 128, BN = 128, BK = 32;
constexpr int TILE_B = BM * BK * 2;                 // 8192 B per matrix tile
constexpr int STAGE  = 4 * TILE_B;                  // Ah,Al,Bh,Bl = 32 KB
constexpr int NSTAGE = 3;
constexpr int SMEM_BYTES = NSTAGE * STAGE;          // 96 KB

__device__ __forceinline__ uint32_t sm_addr(const void* p) {
    uint32_t a;
    asm("{ .reg .u64 t; cvta.to.shared.u64 t, %1; cvt.u32.u64 %0, t; }" : "=r"(a) : "l"(p));
    return a;
}
__device__ __forceinline__ void cpasync16(uint32_t s, const void* g) {
    asm volatile("cp.async.cg.shared.global [%0], [%1], 16;" :: "r"(s), "l"(g));
}
__device__ __forceinline__ void ldmx4(uint32_t& r0, uint32_t& r1, uint32_t& r2, uint32_t& r3,
                                      uint32_t a) {
    asm volatile("ldmatrix.sync.aligned.m8n8.x4.shared.b16 {%0,%1,%2,%3}, [%4];"
                 : "=r"(r0), "=r"(r1), "=r"(r2), "=r"(r3) : "r"(a));
}
__device__ __forceinline__ void mma16816(float* c, const uint32_t* a, const uint32_t* b) {
    asm volatile("mma.sync.aligned.m16n8k16.row.col.f32.f16.f16.f32 "
                 "{%0,%1,%2,%3}, {%4,%5,%6,%7}, {%8,%9}, {%0,%1,%2,%3};"
                 : "+f"(c[0]), "+f"(c[1]), "+f"(c[2]), "+f"(c[3])
                 : "r"(a[0]), "r"(a[1]), "r"(a[2]), "r"(a[3]), "r"(b[0]), "r"(b[1]));
}
__device__ __forceinline__ uint32_t swoff(int row, int j) {
    return row * 64 + ((j ^ ((row >> 1) & 3)) << 4);
}

// ---------------- split-precision fp16 NT GEMM via mma.sync ----------------
// 2 CTAs/SM (regs capped at 128; 2 x 96KB smem). The 3-pass variant reuses the
// A-fragment registers: load a_hi -> hh + hl passes, reload a_lo -> lh pass.
template<int NPASS, bool SPLIT_OUT, bool CSKIP, bool CK>
__global__ __launch_bounds__(256, 2)
void tgemm(const __half* __restrict__ Ah, const __half* __restrict__ Al,
           const __half* __restrict__ Bh, const __half* __restrict__ Bl,
           float* __restrict__ Cf, __half* __restrict__ Ch, __half* __restrict__ Cl,
           int K, int lda, int ldb, int ldc)
{
    const int bx = blockIdx.x, by = blockIdx.y;
    if (CSKIP && bx > by) return;
    const int Keff = CK ? min(K, (by + 1) * BM) : K;
    const int nC = Keff / BK;

    extern __shared__ __align__(1024) char smem[];
    const uint32_t sb = sm_addr(smem);

    const int tid = threadIdx.x;
    const int lane = tid & 31, wid = tid >> 5;
    const int wm = wid & 1, wn = wid >> 1;

    const int lrow = tid >> 1;
    const int ljb  = (tid & 1) * 2;
    const size_t arow = (size_t)(by * BM + lrow) * lda;
    const size_t brow = (size_t)(bx * BN + lrow) * ldb;

    float acc[4][4][4];
    #pragma unroll
    for (int i = 0; i < 4; i++)
        #pragma unroll
        for (int j = 0; j < 4; j++)
            #pragma unroll
            for (int r = 0; r < 4; r++) acc[i][j][r] = 0.f;

    auto issue = [&](int c) {
        const uint32_t s0 = sb + (c % NSTAGE) * STAGE;
        const int kc = c * BK;
        #pragma unroll
        for (int jj = 0; jj < 2; jj++) {
            const int j = ljb + jj;
            const uint32_t so = swoff(lrow, j);
            const size_t ga = arow + kc + j * 8;
            const size_t gb = brow + kc + j * 8;
            cpasync16(s0 + so, Ah + ga);
            if (NPASS == 3) cpasync16(s0 + TILE_B + so, Al + ga);
            cpasync16(s0 + 2 * TILE_B + so, Bh + gb);
            cpasync16(s0 + 3 * TILE_B + so, Bl + gb);
        }
    };

    issue(0); asm volatile("cp.async.commit_group;");
    issue(1); asm volatile("cp.async.commit_group;");

    for (int c = 0; c < nC; c++) {
        asm volatile("cp.async.wait_group 1;");
        __syncthreads();
        if (c + 2 < nC) issue(c + 2);
        asm volatile("cp.async.commit_group;");

        const uint32_t s0 = sb + (c % NSTAGE) * STAGE;
        #pragma unroll
        for (int ks = 0; ks < 2; ks++) {
            uint32_t a[4][4], b_h[4][2], b_l[4][2];
            // A hi fragments
            #pragma unroll
            for (int i = 0; i < 4; i++) {
                const int row = wm * 64 + i * 16 + (lane & 15);
                const int ch  = 2 * ks + (lane >> 4);
                ldmx4(a[i][0], a[i][1], a[i][2], a[i][3], s0 + swoff(row, ch));
            }
            // B hi + lo fragments
            #pragma unroll
            for (int p = 0; p < 2; p++) {
                const int row = wn * 32 + p * 16 + (lane & 7) + ((lane & 16) >> 1);
                const int ch  = 2 * ks + ((lane >> 3) & 1);
                const uint32_t off = swoff(row, ch);
                uint32_t r0, r1, r2, r3;
                ldmx4(r0, r1, r2, r3, s0 + 2 * TILE_B + off);
                b_h[2 * p][0] = r0; b_h[2 * p][1] = r1;
                b_h[2 * p + 1][0] = r2; b_h[2 * p + 1][1] = r3;
                ldmx4(r0, r1, r2, r3, s0 + 3 * TILE_B + off);
                b_l[2 * p][0] = r0; b_l[2 * p][1] = r1;
                b_l[2 * p + 1][0] = r2; b_l[2 * p + 1][1] = r3;
            }
            // hh + hl passes
            #pragma unroll
            for (int i = 0; i < 4; i++)
                #pragma unroll
                for (int j = 0; j < 4; j++) {
                    mma16816(acc[i][j], a[i], b_h[j]);
                    mma16816(acc[i][j], a[i], b_l[j]);
                }
            if (NPASS == 3) {
                // reload same registers with A lo, lh pass
                #pragma unroll
                for (int i = 0; i < 4; i++) {
                    const int row = wm * 64 + i * 16 + (lane & 15);
                    const int ch  = 2 * ks + (lane >> 4);
                    ldmx4(a[i][0], a[i][1], a[i][2], a[i][3],
                          s0 + TILE_B + swoff(row, ch));
                }
                #pragma unroll
                for (int i = 0; i < 4; i++)
                    #pragma unroll
                    for (int j = 0; j < 4; j++)
                        mma16816(acc[i][j], a[i], b_h[j]);
            }
        }
        __syncthreads();
    }

    const int r0 = by * BM + wm * 64 + (lane >> 2);
    const int c0 = bx * BN + wn * 32 + (lane & 3) * 2;
    #pragma unroll
    for (int i = 0; i < 4; i++)
        #pragma unroll
        for (int j = 0; j < 4; j++) {
            const int rr = r0 + i * 16;
            const int cc = c0 + j * 8;
            #pragma unroll
            for (int h = 0; h < 2; h++) {
                const float v0 = acc[i][j][2 * h], v1 = acc[i][j][2 * h + 1];
                const size_t o = (size_t)(rr + 8 * h) * ldc + cc;
                if (!SPLIT_OUT) {
                    *(float2*)(Cf + o) = make_float2(v0, v1);
                } else {
                    __half h0 = __float2half_rn(v0), h1 = __float2half_rn(v1);
                    __half l0 = __float2half_rn(v0 - __half2float(h0));
                    __half l1 = __float2half_rn(v1 - __half2float(h1));
                    *(__half2*)(Ch + o) = __halves2half2(h0, h1);
                    *(__half2*)(Cl + o) = __halves2half2(l0, l1);
                }
            }
        }
}

// ---------------- fp32 -> fp16 hi/lo split ----------------
__global__ __launch_bounds__(256)
void splitk(const float* __restrict__ in, __half* __restrict__ h, __half* __restrict__ l, int n)
{
    int i = (blockIdx.x * 256 + threadIdx.x) * 4;
    if (i >= n) return;
    float4 v = *(const float4*)(in + i);
    __half h0 = __float2half_rn(v.x), h1 = __float2half_rn(v.y);
    __half h2 = __float2half_rn(v.z), h3 = __float2half_rn(v.w);
    __half l0 = __float2half_rn(v.x - __half2float(h0));
    __half l1 = __float2half_rn(v.y - __half2float(h1));
    __half l2 = __float2half_rn(v.z - __half2float(h2));
    __half l3 = __float2half_rn(v.w - __half2float(h3));
    *(__half2*)(h + i)     = __halves2half2(h0, h1);
    *(__half2*)(h + i + 2) = __halves2half2(h2, h3);
    *(__half2*)(l + i)     = __halves2half2(l0, l1);
    *(__half2*)(l + i + 2) = __halves2half2(l2, l3);
}

// ---------------- causal softmax -> sparse (idx, weight) lists ----------------
__device__ __forceinline__ float warpMax(float v) {
    #pragma unroll
    for (int o = 16; o; o >>= 1) v = fmaxf(v, __shfl_xor_sync(0xffffffffu, v, o));
    return v;
}
__device__ __forceinline__ float warpSum(float v) {
    #pragma unroll
    for (int o = 16; o; o >>= 1) v += __shfl_xor_sync(0xffffffffu, v, o);
    return v;
}

// Keep weights with unnormalized exp > e^-18 (~1.52e-8). Z sums ALL terms, so
// retained weights are exact; dropped mass <= 4096 * e^-18 / Z ~ 4e-5.
__global__ __launch_bounds__(256)
void causal_softmax_sparse(const float* __restrict__ S, uint32_t* __restrict__ Widx,
                           float* __restrict__ Wval, int* __restrict__ Cnt, int N)
{
    const int row = blockIdx.x;
    const int len = row + 1;
    const float* Srow = S + (size_t)row * N;
    const int tid = threadIdx.x;

    __shared__ float red[8];
    __shared__ int scnt;
    if (tid == 0) scnt = 0;

    float vals[16];
    int cnt = 0;
    float m = -3.4e38f;
    for (int j = tid; j < len; j += 256) {
        float v = Srow[j];
        vals[cnt++] = v;
        m = fmaxf(m, v);
    }

    m = warpMax(m);
    if ((tid & 31) == 0) red[tid >> 5] = m;
    __syncthreads();
    float bm = red[0];
    #pragma unroll
    for (int w = 1; w < 8; w++) bm = fmaxf(bm, red[w]);
    __syncthreads();

    float sum = 0.f;
    for (int c = 0; c < cnt; c++) {
        float e = __expf(vals[c] - bm);
        vals[c] = e;
        sum += e;
    }
    sum = warpSum(sum);
    if ((tid & 31) == 0) red[tid >> 5] = sum;
    __syncthreads();
    float bs = 0.f;
    #pragma unroll
    for (int w = 0; w < 8; w++) bs += red[w];
    const float inv = 1.0f / bs;

    uint32_t* Wi = Widx + (size_t)row * N;
    float*    Wv = Wval + (size_t)row * N;
    for (int c = 0; c < cnt; c++) {
        const float e = vals[c];
        if (e > 1.523e-8f) {
            const int slot = atomicAdd(&scnt, 1);
            Wi[slot] = tid + c * 256;
            Wv[slot] = e * inv;
        }
    }
    __syncthreads();
    if (tid == 0) Cnt[row] = scnt;
}

// ---------------- sparse z = attn @ x (fp32), emit z hi/lo ----------------
__global__ __launch_bounds__(256)
void sparse_av(const float* __restrict__ x, const uint32_t* __restrict__ Widx,
               const float* __restrict__ Wval, const int* __restrict__ Cnt,
               __half* __restrict__ Zh, __half* __restrict__ Zl)
{
    const int row = blockIdx.x;
    const int c = Cnt[row];
    const int tid = threadIdx.x;

    __shared__ float sw[256];
    __shared__ uint32_t sj[256];

    float acc[8];
    #pragma unroll
    for (int r = 0; r < 8; r++) acc[r] = 0.f;

    const uint32_t* Wi = Widx + (size_t)row * NCTX;
    const float*    Wv = Wval + (size_t)row * NCTX;

    for (int base = 0; base < c; base += 256) {
        const int m = min(256, c - base);
        __syncthreads();
        if (tid < m) { sw[tid] = Wv[base + tid]; sj[tid] = Wi[base + tid]; }
        __syncthreads();
        for (int p = 0; p < m; p++) {
            const float w = sw[p];
            const float* xr = x + (size_t)sj[p] * DMODEL + tid * 8;
            const float4 a = *(const float4*)xr;
            const float4 b = *(const float4*)(xr + 4);
            acc[0] = fmaf(w, a.x, acc[0]); acc[1] = fmaf(w, a.y, acc[1]);
            acc[2] = fmaf(w, a.z, acc[2]); acc[3] = fmaf(w, a.w, acc[3]);
            acc[4] = fmaf(w, b.x, acc[4]); acc[5] = fmaf(w, b.y, acc[5]);
            acc[6] = fmaf(w, b.z, acc[6]); acc[7] = fmaf(w, b.w, acc[7]);
        }
    }

    __half* zh = Zh + (size_t)row * DMODEL + tid * 8;
    __half* zl = Zl + (size_t)row * DMODEL + tid * 8;
    #pragma unroll
    for (int r = 0; r < 8; r += 2) {
        __half h0 = __float2half_rn(acc[r]),     h1 = __float2half_rn(acc[r + 1]);
        __half l0 = __float2half_rn(acc[r] - __half2float(h0));
        __half l1 = __float2half_rn(acc[r + 1] - __half2float(h1));
        *(__half2*)(zh + r) = __halves2half2(h0, h1);
        *(__half2*)(zl + r) = __halves2half2(l0, l1);
    }
}

// ---------------- host ----------------
extern "C" void kernel_launch(void* const* d_in, const int* in_sizes, int n_in,
                              void* d_out, int out_size)
{
    const float* x   = (const float*)d_in[0];
    const float* Wqk = (const float*)d_in[1];
    const float* Wov = (const float*)d_in[2];
    float* out = (float*)d_out;

    float* s;  cudaGetSymbolAddress((void**)&s, g_s);
    __half *xh, *xl, *wqh, *wql, *wvh, *wvl, *qh, *ql, *zh, *zl;
    uint32_t* widx; float* wval; int* cnt;
    cudaGetSymbolAddress((void**)&xh,  g_xh);  cudaGetSymbolAddress((void**)&xl,  g_xl);
    cudaGetSymbolAddress((void**)&wqh, g_wqh); cudaGetSymbolAddress((void**)&wql, g_wql);
    cudaGetSymbolAddress((void**)&wvh, g_wvh); cudaGetSymbolAddress((void**)&wvl, g_wvl);
    cudaGetSymbolAddress((void**)&qh,  g_qh);  cudaGetSymbolAddress((void**)&ql,  g_ql);
    cudaGetSymbolAddress((void**)&zh,  g_zh);  cudaGetSymbolAddress((void**)&zl,  g_zl);
    cudaGetSymbolAddress((void**)&widx, g_widx);
    cudaGetSymbolAddress((void**)&wval, g_wval);
    cudaGetSymbolAddress((void**)&cnt,  g_cnt);

    cudaFuncSetAttribute(tgemm<3, true,  false, false>, cudaFuncAttributeMaxDynamicSharedMemorySize, SMEM_BYTES);
    cudaFuncSetAttribute(tgemm<3, false, true,  false>, cudaFuncAttributeMaxDynamicSharedMemorySize, SMEM_BYTES);
    cudaFuncSetAttribute(tgemm<2, false, false, false>, cudaFuncAttributeMaxDynamicSharedMemorySize, SMEM_BYTES);

    const int nx = NCTX * DMODEL, nw = DMODEL * DMODEL;

    splitk<<<nx / 1024, 256>>>(x,   xh,  xl,  nx);
    splitk<<<nw / 1024, 256>>>(Wqk, wqh, wql, nw);
    splitk<<<nw / 1024, 256>>>(Wov, wvh, wvl, nw);

    // 1) q = x @ Wqk^T  -> q hi/lo (3-pass; feeds scores)
    tgemm<3, true, false, false><<<dim3(DMODEL / BN, NCTX / BM), 256, SMEM_BYTES>>>(
        xh, xl, wqh, wql, nullptr, qh, ql, DMODEL, DMODEL, DMODEL, DMODEL);

    // 2) s = q @ x^T (causal block skip) -> fp32 scores (3-pass)
    tgemm<3, false, true, false><<<dim3(NCTX / BN, NCTX / BM), 256, SMEM_BYTES>>>(
        qh, ql, xh, xl, s, nullptr, nullptr, DMODEL, DMODEL, DMODEL, NCTX);

    // 3) softmax -> sparse (idx, weight) lists
    causal_softmax_sparse<<<NCTX, 256>>>(s, widx, wval, cnt, NCTX);

    // 4) z = attn @ x via sparse gather (fp32 exact) -> z hi/lo
    sparse_av<<<NCTX, 256>>>(x, widx, wval, cnt, zh, zl);

    // 5) out = z @ Wov^T -> fp32 output (2-pass)
    tgemm<2, false, false, false><<<dim3(DMODEL / BN, NCTX / BM), 256, SMEM_BYTES>>>(
        zh, zl, wvh, wvl, out, nullptr, nullptr, DMODEL, DMODEL, DMODEL, DMODEL);
}

// round 7
// speedup vs baseline: 3.7823x; 1.0070x over previous
#include <cuda_runtime.h>
#include <cuda_fp16.h>
#include <cstdint>

#define NCTX 4096
#define DMODEL 2048

// ---------------- scratch (static device globals; no runtime alloc) ----------------
__device__ float g_s[(size_t)NCTX * NCTX];                        // 64 MB scores
__device__ __align__(256) __half g_xh[(size_t)NCTX * DMODEL];
__device__ __align__(256) __half g_xl[(size_t)NCTX * DMODEL];
__device__ __align__(256) __half g_wqh[(size_t)DMODEL * DMODEL];
__device__ __align__(256) __half g_wql[(size_t)DMODEL * DMODEL];
__device__ __align__(256) __half g_wvh[(size_t)DMODEL * DMODEL];
__device__ __align__(256) __half g_wvl[(size_t)DMODEL * DMODEL];
__device__ __align__(256) __half g_qh[(size_t)NCTX * DMODEL];
__device__ __align__(256) __half g_ql[(size_t)NCTX * DMODEL];
__device__ __align__(256) __half g_zh[(size_t)NCTX * DMODEL];
__device__ __align__(256) __half g_zl[(size_t)NCTX * DMODEL];
// sparse attention weights (full 4096/row worst case -> always correct)
__device__ uint32_t g_widx[(size_t)NCTX * NCTX];                  // 64 MB
__device__ float    g_wval[(size_t)NCTX * NCTX];                  // 64 MB
__device__ int      g_cnt[NCTX];

// ---------------- GEMM config ----------------
constexpr int BM = 128, BN = 128, BK = 32;
constexpr int TILE_B = BM * BK * 2;                 // 8192 B per matrix tile
constexpr int STAGE  = 4 * TILE_B;                  // Ah,Al,Bh,Bl = 32 KB
constexpr int NSTAGE = 3;
constexpr int SMEM_BYTES = NSTAGE * STAGE;          // 96 KB

__device__ __forceinline__ uint32_t sm_addr(const void* p) {
    uint32_t a;
    asm("{ .reg .u64 t; cvta.to.shared.u64 t, %1; cvt.u32.u64 %0, t; }" : "=r"(a) : "l"(p));
    return a;
}
__device__ __forceinline__ void cpasync16(uint32_t s, const void* g) {
    asm volatile("cp.async.cg.shared.global [%0], [%1], 16;" :: "r"(s), "l"(g));
}
__device__ __forceinline__ void ldmx4(uint32_t& r0, uint32_t& r1, uint32_t& r2, uint32_t& r3,
                                      uint32_t a) {
    asm volatile("ldmatrix.sync.aligned.m8n8.x4.shared.b16 {%0,%1,%2,%3}, [%4];"
                 : "=r"(r0), "=r"(r1), "=r"(r2), "=r"(r3) : "r"(a));
}
__device__ __forceinline__ void mma16816(float* c, const uint32_t* a, const uint32_t* b) {
    asm volatile("mma.sync.aligned.m16n8k16.row.col.f32.f16.f16.f32 "
                 "{%0,%1,%2,%3}, {%4,%5,%6,%7}, {%8,%9}, {%0,%1,%2,%3};"
                 : "+f"(c[0]), "+f"(c[1]), "+f"(c[2]), "+f"(c[3])
                 : "r"(a[0]), "r"(a[1]), "r"(a[2]), "r"(a[3]), "r"(b[0]), "r"(b[1]));
}
__device__ __forceinline__ uint32_t swoff(int row, int j) {
    return row * 64 + ((j ^ ((row >> 1) & 3)) << 4);
}

// ---------------- split-precision fp16 NT GEMM via mma.sync ----------------
// 2 CTAs/SM. Pass-major MMA order: all hh, then all hl, then all lh —
// accumulator reuses are 16 independent MMAs apart (no RAW stalls).
template<int NPASS, bool SPLIT_OUT, bool CSKIP, bool CK>
__global__ __launch_bounds__(256, 2)
void tgemm(const __half* __restrict__ Ah, const __half* __restrict__ Al,
           const __half* __restrict__ Bh, const __half* __restrict__ Bl,
           float* __restrict__ Cf, __half* __restrict__ Ch, __half* __restrict__ Cl,
           int K, int lda, int ldb, int ldc)
{
    const int bx = blockIdx.x, by = blockIdx.y;
    if (CSKIP && bx > by) return;
    const int Keff = CK ? min(K, (by + 1) * BM) : K;
    const int nC = Keff / BK;

    extern __shared__ __align__(1024) char smem[];
    const uint32_t sb = sm_addr(smem);

    const int tid = threadIdx.x;
    const int lane = tid & 31, wid = tid >> 5;
    const int wm = wid & 1, wn = wid >> 1;

    const int lrow = tid >> 1;
    const int ljb  = (tid & 1) * 2;
    const size_t arow = (size_t)(by * BM + lrow) * lda;
    const size_t brow = (size_t)(bx * BN + lrow) * ldb;

    float acc[4][4][4];
    #pragma unroll
    for (int i = 0; i < 4; i++)
        #pragma unroll
        for (int j = 0; j < 4; j++)
            #pragma unroll
            for (int r = 0; r < 4; r++) acc[i][j][r] = 0.f;

    auto issue = [&](int c) {
        const uint32_t s0 = sb + (c % NSTAGE) * STAGE;
        const int kc = c * BK;
        #pragma unroll
        for (int jj = 0; jj < 2; jj++) {
            const int j = ljb + jj;
            const uint32_t so = swoff(lrow, j);
            const size_t ga = arow + kc + j * 8;
            const size_t gb = brow + kc + j * 8;
            cpasync16(s0 + so, Ah + ga);
            if (NPASS == 3) cpasync16(s0 + TILE_B + so, Al + ga);
            cpasync16(s0 + 2 * TILE_B + so, Bh + gb);
            cpasync16(s0 + 3 * TILE_B + so, Bl + gb);
        }
    };

    issue(0); asm volatile("cp.async.commit_group;");
    issue(1); asm volatile("cp.async.commit_group;");

    for (int c = 0; c < nC; c++) {
        asm volatile("cp.async.wait_group 1;");
        __syncthreads();
        if (c + 2 < nC) issue(c + 2);
        asm volatile("cp.async.commit_group;");

        const uint32_t s0 = sb + (c % NSTAGE) * STAGE;
        #pragma unroll
        for (int ks = 0; ks < 2; ks++) {
            uint32_t a[4][4], b_h[4][2], b_l[4][2];
            // A hi fragments
            #pragma unroll
            for (int i = 0; i < 4; i++) {
                const int row = wm * 64 + i * 16 + (lane & 15);
                const int ch  = 2 * ks + (lane >> 4);
                ldmx4(a[i][0], a[i][1], a[i][2], a[i][3], s0 + swoff(row, ch));
            }
            // B hi + lo fragments
            #pragma unroll
            for (int p = 0; p < 2; p++) {
                const int row = wn * 32 + p * 16 + (lane & 7) + ((lane & 16) >> 1);
                const int ch  = 2 * ks + ((lane >> 3) & 1);
                const uint32_t off = swoff(row, ch);
                uint32_t r0, r1, r2, r3;
                ldmx4(r0, r1, r2, r3, s0 + 2 * TILE_B + off);
                b_h[2 * p][0] = r0; b_h[2 * p][1] = r1;
                b_h[2 * p + 1][0] = r2; b_h[2 * p + 1][1] = r3;
                ldmx4(r0, r1, r2, r3, s0 + 3 * TILE_B + off);
                b_l[2 * p][0] = r0; b_l[2 * p][1] = r1;
                b_l[2 * p + 1][0] = r2; b_l[2 * p + 1][1] = r3;
            }
            // pass-major order: hh sweep, then hl sweep (16 indep MMAs between acc reuse)
            #pragma unroll
            for (int i = 0; i < 4; i++)
                #pragma unroll
                for (int j = 0; j < 4; j++)
                    mma16816(acc[i][j], a[i], b_h[j]);
            #pragma unroll
            for (int i = 0; i < 4; i++)
                #pragma unroll
                for (int j = 0; j < 4; j++)
                    mma16816(acc[i][j], a[i], b_l[j]);
            if (NPASS == 3) {
                // reload same registers with A lo, lh sweep
                #pragma unroll
                for (int i = 0; i < 4; i++) {
                    const int row = wm * 64 + i * 16 + (lane & 15);
                    const int ch  = 2 * ks + (lane >> 4);
                    ldmx4(a[i][0], a[i][1], a[i][2], a[i][3],
                          s0 + TILE_B + swoff(row, ch));
                }
                #pragma unroll
                for (int i = 0; i < 4; i++)
                    #pragma unroll
                    for (int j = 0; j < 4; j++)
                        mma16816(acc[i][j], a[i], b_h[j]);
            }
        }
        // NOTE: no trailing __syncthreads — the next iteration's top sync already
        // orders buffer reuse (3-stage ring: issue(c+3) waits on that sync).
    }

    const int r0 = by * BM + wm * 64 + (lane >> 2);
    const int c0 = bx * BN + wn * 32 + (lane & 3) * 2;
    #pragma unroll
    for (int i = 0; i < 4; i++)
        #pragma unroll
        for (int j = 0; j < 4; j++) {
            const int rr = r0 + i * 16;
            const int cc = c0 + j * 8;
            #pragma unroll
            for (int h = 0; h < 2; h++) {
                const float v0 = acc[i][j][2 * h], v1 = acc[i][j][2 * h + 1];
                const size_t o = (size_t)(rr + 8 * h) * ldc + cc;
                if (!SPLIT_OUT) {
                    *(float2*)(Cf + o) = make_float2(v0, v1);
                } else {
                    __half h0 = __float2half_rn(v0), h1 = __float2half_rn(v1);
                    __half l0 = __float2half_rn(v0 - __half2float(h0));
                    __half l1 = __float2half_rn(v1 - __half2float(h1));
                    *(__half2*)(Ch + o) = __halves2half2(h0, h1);
                    *(__half2*)(Cl + o) = __halves2half2(l0, l1);
                }
            }
        }
}

// ---------------- fp32 -> fp16 hi/lo split ----------------
__global__ __launch_bounds__(256)
void splitk(const float* __restrict__ in, __half* __restrict__ h, __half* __restrict__ l, int n)
{
    int i = (blockIdx.x * 256 + threadIdx.x) * 4;
    if (i >= n) return;
    float4 v = *(const float4*)(in + i);
    __half h0 = __float2half_rn(v.x), h1 = __float2half_rn(v.y);
    __half h2 = __float2half_rn(v.z), h3 = __float2half_rn(v.w);
    __half l0 = __float2half_rn(v.x - __half2float(h0));
    __half l1 = __float2half_rn(v.y - __half2float(h1));
    __half l2 = __float2half_rn(v.z - __half2float(h2));
    __half l3 = __float2half_rn(v.w - __half2float(h3));
    *(__half2*)(h + i)     = __halves2half2(h0, h1);
    *(__half2*)(h + i + 2) = __halves2half2(h2, h3);
    *(__half2*)(l + i)     = __halves2half2(l0, l1);
    *(__half2*)(l + i + 2) = __halves2half2(l2, l3);
}

// ---------------- causal softmax -> sparse (idx, weight) lists ----------------
__device__ __forceinline__ float warpMax(float v) {
    #pragma unroll
    for (int o = 16; o; o >>= 1) v = fmaxf(v, __shfl_xor_sync(0xffffffffu, v, o));
    return v;
}
__device__ __forceinline__ float warpSum(float v) {
    #pragma unroll
    for (int o = 16; o; o >>= 1) v += __shfl_xor_sync(0xffffffffu, v, o);
    return v;
}

// Keep weights with unnormalized exp > e^-18 (~1.52e-8). Z sums ALL terms, so
// retained weights are exact; dropped mass <= 4096 * e^-18 / Z ~ 4e-5.
__global__ __launch_bounds__(256)
void causal_softmax_sparse(const float* __restrict__ S, uint32_t* __restrict__ Widx,
                           float* __restrict__ Wval, int* __restrict__ Cnt, int N)
{
    const int row = blockIdx.x;
    const int len = row + 1;
    const float* Srow = S + (size_t)row * N;
    const int tid = threadIdx.x;

    __shared__ float red[8];
    __shared__ int scnt;
    if (tid == 0) scnt = 0;

    float vals[16];
    int cnt = 0;
    float m = -3.4e38f;
    for (int j = tid; j < len; j += 256) {
        float v = Srow[j];
        vals[cnt++] = v;
        m = fmaxf(m, v);
    }

    m = warpMax(m);
    if ((tid & 31) == 0) red[tid >> 5] = m;
    __syncthreads();
    float bm = red[0];
    #pragma unroll
    for (int w = 1; w < 8; w++) bm = fmaxf(bm, red[w]);
    __syncthreads();

    float sum = 0.f;
    for (int c = 0; c < cnt; c++) {
        float e = __expf(vals[c] - bm);
        vals[c] = e;
        sum += e;
    }
    sum = warpSum(sum);
    if ((tid & 31) == 0) red[tid >> 5] = sum;
    __syncthreads();
    float bs = 0.f;
    #pragma unroll
    for (int w = 0; w < 8; w++) bs += red[w];
    const float inv = 1.0f / bs;

    uint32_t* Wi = Widx + (size_t)row * N;
    float*    Wv = Wval + (size_t)row * N;
    for (int c = 0; c < cnt; c++) {
        const float e = vals[c];
        if (e > 1.523e-8f) {
            const int slot = atomicAdd(&scnt, 1);
            Wi[slot] = tid + c * 256;
            Wv[slot] = e * inv;
        }
    }
    __syncthreads();
    if (tid == 0) Cnt[row] = scnt;
}

// ---------------- sparse z = attn @ x (fp32), emit z hi/lo ----------------
__global__ __launch_bounds__(256)
void sparse_av(const float* __restrict__ x, const uint32_t* __restrict__ Widx,
               const float* __restrict__ Wval, const int* __restrict__ Cnt,
               __half* __restrict__ Zh, __half* __restrict__ Zl)
{
    const int row = blockIdx.x;
    const int c = Cnt[row];
    const int tid = threadIdx.x;

    __shared__ float sw[256];
    __shared__ uint32_t sj[256];

    float acc[8];
    #pragma unroll
    for (int r = 0; r < 8; r++) acc[r] = 0.f;

    const uint32_t* Wi = Widx + (size_t)row * NCTX;
    const float*    Wv = Wval + (size_t)row * NCTX;

    for (int base = 0; base < c; base += 256) {
        const int m = min(256, c - base);
        __syncthreads();
        if (tid < m) { sw[tid] = Wv[base + tid]; sj[tid] = Wi[base + tid]; }
        __syncthreads();
        for (int p = 0; p < m; p++) {
            const float w = sw[p];
            const float* xr = x + (size_t)sj[p] * DMODEL + tid * 8;
            const float4 a = *(const float4*)xr;
            const float4 b = *(const float4*)(xr + 4);
            acc[0] = fmaf(w, a.x, acc[0]); acc[1] = fmaf(w, a.y, acc[1]);
            acc[2] = fmaf(w, a.z, acc[2]); acc[3] = fmaf(w, a.w, acc[3]);
            acc[4] = fmaf(w, b.x, acc[4]); acc[5] = fmaf(w, b.y, acc[5]);
            acc[6] = fmaf(w, b.z, acc[6]); acc[7] = fmaf(w, b.w, acc[7]);
        }
    }

    __half* zh = Zh + (size_t)row * DMODEL + tid * 8;
    __half* zl = Zl + (size_t)row * DMODEL + tid * 8;
    #pragma unroll
    for (int r = 0; r < 8; r += 2) {
        __half h0 = __float2half_rn(acc[r]),     h1 = __float2half_rn(acc[r + 1]);
        __half l0 = __float2half_rn(acc[r] - __half2float(h0));
        __half l1 = __float2half_rn(acc[r + 1] - __half2float(h1));
        *(__half2*)(zh + r) = __halves2half2(h0, h1);
        *(__half2*)(zl + r) = __halves2half2(l0, l1);
    }
}

// ---------------- host ----------------
extern "C" void kernel_launch(void* const* d_in, const int* in_sizes, int n_in,
                              void* d_out, int out_size)
{
    const float* x   = (const float*)d_in[0];
    const float* Wqk = (const float*)d_in[1];
    const float* Wov = (const float*)d_in[2];
    float* out = (float*)d_out;

    float* s;  cudaGetSymbolAddress((void**)&s, g_s);
    __half *xh, *xl, *wqh, *wql, *wvh, *wvl, *qh, *ql, *zh, *zl;
    uint32_t* widx; float* wval; int* cnt;
    cudaGetSymbolAddress((void**)&xh,  g_xh);  cudaGetSymbolAddress((void**)&xl,  g_xl);
    cudaGetSymbolAddress((void**)&wqh, g_wqh); cudaGetSymbolAddress((void**)&wql, g_wql);
    cudaGetSymbolAddress((void**)&wvh, g_wvh); cudaGetSymbolAddress((void**)&wvl, g_wvl);
    cudaGetSymbolAddress((void**)&qh,  g_qh);  cudaGetSymbolAddress((void**)&ql,  g_ql);
    cudaGetSymbolAddress((void**)&zh,  g_zh);  cudaGetSymbolAddress((void**)&zl,  g_zl);
    cudaGetSymbolAddress((void**)&widx, g_widx);
    cudaGetSymbolAddress((void**)&wval, g_wval);
    cudaGetSymbolAddress((void**)&cnt,  g_cnt);

    cudaFuncSetAttribute(tgemm<3, true,  false, false>, cudaFuncAttributeMaxDynamicSharedMemorySize, SMEM_BYTES);
    cudaFuncSetAttribute(tgemm<3, false, true,  false>, cudaFuncAttributeMaxDynamicSharedMemorySize, SMEM_BYTES);
    cudaFuncSetAttribute(tgemm<2, false, false, false>, cudaFuncAttributeMaxDynamicSharedMemorySize, SMEM_BYTES);

    const int nx = NCTX * DMODEL, nw = DMODEL * DMODEL;

    splitk<<<nx / 1024, 256>>>(x,   xh,  xl,  nx);
    splitk<<<nw / 1024, 256>>>(Wqk, wqh, wql, nw);
    splitk<<<nw / 1024, 256>>>(Wov, wvh, wvl, nw);

    // 1) q = x @ Wqk^T  -> q hi/lo (3-pass; feeds scores)
    tgemm<3, true, false, false><<<dim3(DMODEL / BN, NCTX / BM), 256, SMEM_BYTES>>>(
        xh, xl, wqh, wql, nullptr, qh, ql, DMODEL, DMODEL, DMODEL, DMODEL);

    // 2) s = q @ x^T (causal block skip) -> fp32 scores (3-pass)
    tgemm<3, false, true, false><<<dim3(NCTX / BN, NCTX / BM), 256, SMEM_BYTES>>>(
        qh, ql, xh, xl, s, nullptr, nullptr, DMODEL, DMODEL, DMODEL, NCTX);

    // 3) softmax -> sparse (idx, weight) lists
    causal_softmax_sparse<<<NCTX, 256>>>(s, widx, wval, cnt, NCTX);

    // 4) z = attn @ x via sparse gather (fp32 exact) -> z hi/lo
    sparse_av<<<NCTX, 256>>>(x, widx, wval, cnt, zh, zl);

    // 5) out = z @ Wov^T -> fp32 output (2-pass)
    tgemm<2, false, false, false><<<dim3(DMODEL / BN, NCTX / BM), 256, SMEM_BYTES>>>(
        zh, zl, wvh, wvl, out, nullptr, nullptr, DMODEL, DMODEL, DMODEL, DMODEL);
}

// round 8
// speedup vs baseline: 4.3547x; 1.1513x over previous
#include <cuda_runtime.h>
#include <cuda_fp16.h>
#include <cstdint>

#define NCTX 4096
#define DMODEL 2048

// ---------------- scratch (static device globals; no runtime alloc) ----------------
__device__ float g_s[(size_t)NCTX * NCTX];                        // 64 MB approx scores
__device__ __align__(256) __half g_xh[(size_t)NCTX * DMODEL];
__device__ __align__(256) __half g_xl[(size_t)NCTX * DMODEL];
__device__ __align__(256) __half g_wqh[(size_t)DMODEL * DMODEL];
__device__ __align__(256) __half g_wql[(size_t)DMODEL * DMODEL];
__device__ __align__(256) __half g_wvh[(size_t)DMODEL * DMODEL];
__device__ __align__(256) __half g_wvl[(size_t)DMODEL * DMODEL];
__device__ __align__(256) __half g_qh[(size_t)NCTX * DMODEL];
__device__ __align__(256) __half g_ql[(size_t)NCTX * DMODEL];
__device__ __align__(256) __half g_zh[(size_t)NCTX * DMODEL];
__device__ __align__(256) __half g_zl[(size_t)NCTX * DMODEL];
// sparse attention weights (full 4096/row worst case -> always correct)
__device__ uint32_t g_widx[(size_t)NCTX * NCTX];                  // 64 MB
__device__ float    g_wval[(size_t)NCTX * NCTX];                  // 64 MB
__device__ int      g_cnt[NCTX];

// ---------------- GEMM config ----------------
constexpr int BM = 128, BN = 128, BK = 32;
constexpr int TILE_B = BM * BK * 2;                 // 8192 B per matrix tile
constexpr int STAGE  = 4 * TILE_B;                  // Ah,Al,Bh,Bl slots = 32 KB
constexpr int NSTAGE = 3;
constexpr int SMEM_BYTES = NSTAGE * STAGE;          // 96 KB

__device__ __forceinline__ uint32_t sm_addr(const void* p) {
    uint32_t a;
    asm("{ .reg .u64 t; cvta.to.shared.u64 t, %1; cvt.u32.u64 %0, t; }" : "=r"(a) : "l"(p));
    return a;
}
__device__ __forceinline__ void cpasync16(uint32_t s, const void* g) {
    asm volatile("cp.async.cg.shared.global [%0], [%1], 16;" :: "r"(s), "l"(g));
}
__device__ __forceinline__ void ldmx4(uint32_t& r0, uint32_t& r1, uint32_t& r2, uint32_t& r3,
                                      uint32_t a) {
    asm volatile("ldmatrix.sync.aligned.m8n8.x4.shared.b16 {%0,%1,%2,%3}, [%4];"
                 : "=r"(r0), "=r"(r1), "=r"(r2), "=r"(r3) : "r"(a));
}
__device__ __forceinline__ void mma16816(float* c, const uint32_t* a, const uint32_t* b) {
    asm volatile("mma.sync.aligned.m16n8k16.row.col.f32.f16.f16.f32 "
                 "{%0,%1,%2,%3}, {%4,%5,%6,%7}, {%8,%9}, {%0,%1,%2,%3};"
                 : "+f"(c[0]), "+f"(c[1]), "+f"(c[2]), "+f"(c[3])
                 : "r"(a[0]), "r"(a[1]), "r"(a[2]), "r"(a[3]), "r"(b[0]), "r"(b[1]));
}
__device__ __forceinline__ uint32_t swoff(int row, int j) {
    return row * 64 + ((j ^ ((row >> 1) & 3)) << 4);
}

// ---------------- split-precision fp16 NT GEMM via mma.sync ----------------
// NPASS==3: hh+hl+lh.  NPASS==2: hh+hl.  NPASS==1: hh only (screening precision).
template<int NPASS, bool SPLIT_OUT, bool CSKIP, bool CK>
__global__ __launch_bounds__(256, 2)
void tgemm(const __half* __restrict__ Ah, const __half* __restrict__ Al,
           const __half* __restrict__ Bh, const __half* __restrict__ Bl,
           float* __restrict__ Cf, __half* __restrict__ Ch, __half* __restrict__ Cl,
           int K, int lda, int ldb, int ldc)
{
    const int bx = blockIdx.x, by = blockIdx.y;
    if (CSKIP && bx > by) return;
    const int Keff = CK ? min(K, (by + 1) * BM) : K;
    const int nC = Keff / BK;

    extern __shared__ __align__(1024) char smem[];
    const uint32_t sb = sm_addr(smem);

    const int tid = threadIdx.x;
    const int lane = tid & 31, wid = tid >> 5;
    const int wm = wid & 1, wn = wid >> 1;

    const int lrow = tid >> 1;
    const int ljb  = (tid & 1) * 2;
    const size_t arow = (size_t)(by * BM + lrow) * lda;
    const size_t brow = (size_t)(bx * BN + lrow) * ldb;

    float acc[4][4][4];
    #pragma unroll
    for (int i = 0; i < 4; i++)
        #pragma unroll
        for (int j = 0; j < 4; j++)
            #pragma unroll
            for (int r = 0; r < 4; r++) acc[i][j][r] = 0.f;

    auto issue = [&](int c) {
        const uint32_t s0 = sb + (c % NSTAGE) * STAGE;
        const int kc = c * BK;
        #pragma unroll
        for (int jj = 0; jj < 2; jj++) {
            const int j = ljb + jj;
            const uint32_t so = swoff(lrow, j);
            const size_t ga = arow + kc + j * 8;
            const size_t gb = brow + kc + j * 8;
            cpasync16(s0 + so, Ah + ga);
            if (NPASS == 3) cpasync16(s0 + TILE_B + so, Al + ga);
            cpasync16(s0 + 2 * TILE_B + so, Bh + gb);
            if (NPASS >= 2) cpasync16(s0 + 3 * TILE_B + so, Bl + gb);
        }
    };

    issue(0); asm volatile("cp.async.commit_group;");
    issue(1); asm volatile("cp.async.commit_group;");

    for (int c = 0; c < nC; c++) {
        asm volatile("cp.async.wait_group 1;");
        __syncthreads();
        if (c + 2 < nC) issue(c + 2);
        asm volatile("cp.async.commit_group;");

        const uint32_t s0 = sb + (c % NSTAGE) * STAGE;
        #pragma unroll
        for (int ks = 0; ks < 2; ks++) {
            uint32_t a[4][4], b_h[4][2], b_l[4][2];
            #pragma unroll
            for (int i = 0; i < 4; i++) {
                const int row = wm * 64 + i * 16 + (lane & 15);
                const int ch  = 2 * ks + (lane >> 4);
                ldmx4(a[i][0], a[i][1], a[i][2], a[i][3], s0 + swoff(row, ch));
            }
            #pragma unroll
            for (int p = 0; p < 2; p++) {
                const int row = wn * 32 + p * 16 + (lane & 7) + ((lane & 16) >> 1);
                const int ch  = 2 * ks + ((lane >> 3) & 1);
                const uint32_t off = swoff(row, ch);
                uint32_t r0, r1, r2, r3;
                ldmx4(r0, r1, r2, r3, s0 + 2 * TILE_B + off);
                b_h[2 * p][0] = r0; b_h[2 * p][1] = r1;
                b_h[2 * p + 1][0] = r2; b_h[2 * p + 1][1] = r3;
                if (NPASS >= 2) {
                    ldmx4(r0, r1, r2, r3, s0 + 3 * TILE_B + off);
                    b_l[2 * p][0] = r0; b_l[2 * p][1] = r1;
                    b_l[2 * p + 1][0] = r2; b_l[2 * p + 1][1] = r3;
                }
            }
            #pragma unroll
            for (int i = 0; i < 4; i++)
                #pragma unroll
                for (int j = 0; j < 4; j++)
                    mma16816(acc[i][j], a[i], b_h[j]);
            if (NPASS >= 2) {
                #pragma unroll
                for (int i = 0; i < 4; i++)
                    #pragma unroll
                    for (int j = 0; j < 4; j++)
                        mma16816(acc[i][j], a[i], b_l[j]);
            }
            if (NPASS == 3) {
                #pragma unroll
                for (int i = 0; i < 4; i++) {
                    const int row = wm * 64 + i * 16 + (lane & 15);
                    const int ch  = 2 * ks + (lane >> 4);
                    ldmx4(a[i][0], a[i][1], a[i][2], a[i][3],
                          s0 + TILE_B + swoff(row, ch));
                }
                #pragma unroll
                for (int i = 0; i < 4; i++)
                    #pragma unroll
                    for (int j = 0; j < 4; j++)
                        mma16816(acc[i][j], a[i], b_h[j]);
            }
        }
    }

    const int r0 = by * BM + wm * 64 + (lane >> 2);
    const int c0 = bx * BN + wn * 32 + (lane & 3) * 2;
    #pragma unroll
    for (int i = 0; i < 4; i++)
        #pragma unroll
        for (int j = 0; j < 4; j++) {
            const int rr = r0 + i * 16;
            const int cc = c0 + j * 8;
            #pragma unroll
            for (int h = 0; h < 2; h++) {
                const float v0 = acc[i][j][2 * h], v1 = acc[i][j][2 * h + 1];
                const size_t o = (size_t)(rr + 8 * h) * ldc + cc;
                if (!SPLIT_OUT) {
                    *(float2*)(Cf + o) = make_float2(v0, v1);
                } else {
                    __half h0 = __float2half_rn(v0), h1 = __float2half_rn(v1);
                    __half l0 = __float2half_rn(v0 - __half2float(h0));
                    __half l1 = __float2half_rn(v1 - __half2float(h1));
                    *(__half2*)(Ch + o) = __halves2half2(h0, h1);
                    *(__half2*)(Cl + o) = __halves2half2(l0, l1);
                }
            }
        }
}

// ---------------- fp32 -> fp16 hi/lo split ----------------
__global__ __launch_bounds__(256)
void splitk(const float* __restrict__ in, __half* __restrict__ h, __half* __restrict__ l, int n)
{
    int i = (blockIdx.x * 256 + threadIdx.x) * 4;
    if (i >= n) return;
    float4 v = *(const float4*)(in + i);
    __half h0 = __float2half_rn(v.x), h1 = __float2half_rn(v.y);
    __half h2 = __float2half_rn(v.z), h3 = __float2half_rn(v.w);
    __half l0 = __float2half_rn(v.x - __half2float(h0));
    __half l1 = __float2half_rn(v.y - __half2float(h1));
    __half l2 = __float2half_rn(v.z - __half2float(h2));
    __half l3 = __float2half_rn(v.w - __half2float(h3));
    *(__half2*)(h + i)     = __halves2half2(h0, h1);
    *(__half2*)(h + i + 2) = __halves2half2(h2, h3);
    *(__half2*)(l + i)     = __halves2half2(l0, l1);
    *(__half2*)(l + i + 2) = __halves2half2(l2, l3);
}

// ---------------- reductions ----------------
__device__ __forceinline__ float warpMax(float v) {
    #pragma unroll
    for (int o = 16; o; o >>= 1) v = fmaxf(v, __shfl_xor_sync(0xffffffffu, v, o));
    return v;
}
__device__ __forceinline__ float warpSum(float v) {
    #pragma unroll
    for (int o = 16; o; o >>= 1) v += __shfl_xor_sync(0xffffffffu, v, o);
    return v;
}

// ---------------- screening softmax with exact rescoring ----------------
// Approx scores S (1-pass fp16 GEMM, abs err <~0.05). Candidates within 18.6 of
// the approx row max get EXACT fp32 rescoring (q = qh+ql vs fp32 x). Softmax
// over exact candidate scores + approximate tail (mass < 5e-5). Emits sparse
// (idx, weight) lists. Candidate list holds 4096 -> correct in the worst case.
__global__ __launch_bounds__(256)
void softmax_exact_sparse(const float* __restrict__ S, const __half* __restrict__ Qh,
                          const __half* __restrict__ Ql, const float* __restrict__ x,
                          uint32_t* __restrict__ Widx, float* __restrict__ Wval,
                          int* __restrict__ Cnt, int N)
{
    const int row = blockIdx.x;
    const int len = row + 1;
    const float* Srow = S + (size_t)row * N;
    const int tid = threadIdx.x;
    const int lane = tid & 31, wid = tid >> 5;

    __shared__ float red[8];
    __shared__ int scnt;
    __shared__ uint32_t cidx[NCTX];     // 16 KB
    __shared__ float    csc[NCTX];      // 16 KB
    __shared__ float    qs[DMODEL];     // 8 KB
    if (tid == 0) scnt = 0;

    // Phase A: approx row max
    float m = -3.4e38f;
    for (int j = tid; j < len; j += 256) m = fmaxf(m, Srow[j]);
    m = warpMax(m);
    if (lane == 0) red[wid] = m;
    __syncthreads();
    float ma = red[0];
    #pragma unroll
    for (int w = 1; w < 8; w++) ma = fmaxf(ma, red[w]);
    __syncthreads();

    // Phase B: collect candidates; accumulate approximate tail mass (rel. ma)
    const float thr = ma - 18.6f;
    float tail = 0.f;
    for (int j = tid; j < len; j += 256) {
        const float v = Srow[j];
        if (v > thr) {
            const int slot = atomicAdd(&scnt, 1);
            cidx[slot] = j;
        } else {
            tail += __expf(v - ma);
        }
    }
    tail = warpSum(tail);
    if (lane == 0) red[wid] = tail;
    // Phase C: q row into smem (fp32 = qh + ql)
    const __half* qhr = Qh + (size_t)row * DMODEL;
    const __half* qlr = Ql + (size_t)row * DMODEL;
    __syncthreads();
    float tsum = 0.f;
    #pragma unroll
    for (int w = 0; w < 8; w++) tsum += red[w];
    for (int k = tid; k < DMODEL; k += 256)
        qs[k] = __half2float(qhr[k]) + __half2float(qlr[k]);
    __syncthreads();

    // Phase D: exact rescoring, one warp per candidate
    const int nc = scnt;
    for (int c = wid; c < nc; c += 8) {
        const float* xr = x + (size_t)cidx[c] * DMODEL;
        float p = 0.f;
        #pragma unroll 4
        for (int k = lane; k < DMODEL; k += 32) p = fmaf(qs[k], xr[k], p);
        p = warpSum(p);
        if (lane == 0) csc[c] = p;
    }
    __syncthreads();

    // Phase E: exact max over candidates
    float mx = -3.4e38f;
    for (int c = tid; c < nc; c += 256) mx = fmaxf(mx, csc[c]);
    mx = warpMax(mx);
    if (lane == 0) red[wid] = mx;
    __syncthreads();
    float me = red[0];
    #pragma unroll
    for (int w = 1; w < 8; w++) me = fmaxf(me, red[w]);
    __syncthreads();

    // Phase F: Z = exact candidate mass + rescaled approximate tail
    float zs = 0.f;
    for (int c = tid; c < nc; c += 256) zs += __expf(csc[c] - me);
    zs = warpSum(zs);
    if (lane == 0) red[wid] = zs;
    __syncthreads();
    float Z = tsum * __expf(ma - me);
    #pragma unroll
    for (int w = 0; w < 8; w++) Z += red[w];
    const float inv = 1.0f / Z;

    // Phase G: emit sparse list
    uint32_t* Wi = Widx + (size_t)row * N;
    float*    Wv = Wval + (size_t)row * N;
    for (int c = tid; c < nc; c += 256) {
        Wi[c] = cidx[c];
        Wv[c] = __expf(csc[c] - me) * inv;
    }
    if (tid == 0) Cnt[row] = nc;
}

// ---------------- sparse z = attn @ x (fp32), emit z hi/lo ----------------
__global__ __launch_bounds__(256)
void sparse_av(const float* __restrict__ x, const uint32_t* __restrict__ Widx,
               const float* __restrict__ Wval, const int* __restrict__ Cnt,
               __half* __restrict__ Zh, __half* __restrict__ Zl)
{
    const int row = blockIdx.x;
    const int c = Cnt[row];
    const int tid = threadIdx.x;

    __shared__ float sw[256];
    __shared__ uint32_t sj[256];

    float acc[8];
    #pragma unroll
    for (int r = 0; r < 8; r++) acc[r] = 0.f;

    const uint32_t* Wi = Widx + (size_t)row * NCTX;
    const float*    Wv = Wval + (size_t)row * NCTX;

    for (int base = 0; base < c; base += 256) {
        const int m = min(256, c - base);
        __syncthreads();
        if (tid < m) { sw[tid] = Wv[base + tid]; sj[tid] = Wi[base + tid]; }
        __syncthreads();
        for (int p = 0; p < m; p++) {
            const float w = sw[p];
            const float* xr = x + (size_t)sj[p] * DMODEL + tid * 8;
            const float4 a = *(const float4*)xr;
            const float4 b = *(const float4*)(xr + 4);
            acc[0] = fmaf(w, a.x, acc[0]); acc[1] = fmaf(w, a.y, acc[1]);
            acc[2] = fmaf(w, a.z, acc[2]); acc[3] = fmaf(w, a.w, acc[3]);
            acc[4] = fmaf(w, b.x, acc[4]); acc[5] = fmaf(w, b.y, acc[5]);
            acc[6] = fmaf(w, b.z, acc[6]); acc[7] = fmaf(w, b.w, acc[7]);
        }
    }

    __half* zh = Zh + (size_t)row * DMODEL + tid * 8;
    __half* zl = Zl + (size_t)row * DMODEL + tid * 8;
    #pragma unroll
    for (int r = 0; r < 8; r += 2) {
        __half h0 = __float2half_rn(acc[r]),     h1 = __float2half_rn(acc[r + 1]);
        __half l0 = __float2half_rn(acc[r] - __half2float(h0));
        __half l1 = __float2half_rn(acc[r + 1] - __half2float(h1));
        *(__half2*)(zh + r) = __halves2half2(h0, h1);
        *(__half2*)(zl + r) = __halves2half2(l0, l1);
    }
}

// ---------------- host ----------------
extern "C" void kernel_launch(void* const* d_in, const int* in_sizes, int n_in,
                              void* d_out, int out_size)
{
    const float* x   = (const float*)d_in[0];
    const float* Wqk = (const float*)d_in[1];
    const float* Wov = (const float*)d_in[2];
    float* out = (float*)d_out;

    float* s;  cudaGetSymbolAddress((void**)&s, g_s);
    __half *xh, *xl, *wqh, *wql, *wvh, *wvl, *qh, *ql, *zh, *zl;
    uint32_t* widx; float* wval; int* cnt;
    cudaGetSymbolAddress((void**)&xh,  g_xh);  cudaGetSymbolAddress((void**)&xl,  g_xl);
    cudaGetSymbolAddress((void**)&wqh, g_wqh); cudaGetSymbolAddress((void**)&wql, g_wql);
    cudaGetSymbolAddress((void**)&wvh, g_wvh); cudaGetSymbolAddress((void**)&wvl, g_wvl);
    cudaGetSymbolAddress((void**)&qh,  g_qh);  cudaGetSymbolAddress((void**)&ql,  g_ql);
    cudaGetSymbolAddress((void**)&zh,  g_zh);  cudaGetSymbolAddress((void**)&zl,  g_zl);
    cudaGetSymbolAddress((void**)&widx, g_widx);
    cudaGetSymbolAddress((void**)&wval, g_wval);
    cudaGetSymbolAddress((void**)&cnt,  g_cnt);

    cudaFuncSetAttribute(tgemm<3, true,  false, false>, cudaFuncAttributeMaxDynamicSharedMemorySize, SMEM_BYTES);
    cudaFuncSetAttribute(tgemm<1, false, true,  false>, cudaFuncAttributeMaxDynamicSharedMemorySize, SMEM_BYTES);
    cudaFuncSetAttribute(tgemm<2, false, false, false>, cudaFuncAttributeMaxDynamicSharedMemorySize, SMEM_BYTES);

    const int nx = NCTX * DMODEL, nw = DMODEL * DMODEL;

    splitk<<<nx / 1024, 256>>>(x,   xh,  xl,  nx);
    splitk<<<nw / 1024, 256>>>(Wqk, wqh, wql, nw);
    splitk<<<nw / 1024, 256>>>(Wov, wvh, wvl, nw);

    // 1) q = x @ Wqk^T  -> q hi/lo (3-pass; feeds exact rescoring)
    tgemm<3, true, false, false><<<dim3(DMODEL / BN, NCTX / BM), 256, SMEM_BYTES>>>(
        xh, xl, wqh, wql, nullptr, qh, ql, DMODEL, DMODEL, DMODEL, DMODEL);

    // 2) s~ = qh @ xh^T (1-pass screening; causal block skip) -> fp32 approx scores
    tgemm<1, false, true, false><<<dim3(NCTX / BN, NCTX / BM), 256, SMEM_BYTES>>>(
        qh, nullptr, xh, nullptr, s, nullptr, nullptr, DMODEL, DMODEL, DMODEL, NCTX);

    // 3) screening softmax + exact rescoring -> sparse (idx, weight)
    softmax_exact_sparse<<<NCTX, 256>>>(s, qh, ql, x, widx, wval, cnt, NCTX);

    // 4) z = attn @ x via sparse gather (fp32 exact) -> z hi/lo
    sparse_av<<<NCTX, 256>>>(x, widx, wval, cnt, zh, zl);

    // 5) out = z @ Wov^T -> fp32 output (2-pass)
    tgemm<2, false, false, false><<<dim3(DMODEL / BN, NCTX / BM), 256, SMEM_BYTES>>>(
        zh, zl, wvh, wvl, out, nullptr, nullptr, DMODEL, DMODEL, DMODEL, DMODEL);
}